// round 10
// baseline (speedup 1.0000x reference)
#include <cuda_runtime.h>
#include <cuda_bf16.h>
#include <math.h>
#include <stdint.h>

#define BSZ 2
#define SEQ 2048
#define EMB 2048
#define NH  32
#define NKV 8
#define HD  64
#define KVD (NKV * HD)   // 512
#define QKVN (EMB + 2 * KVD)   // 3072

// ---------------- scratch (static device memory; no allocs allowed) ----------
__device__ float g_qkv_lin[BSZ * SEQ * QKVN];       // x@[Wq|Wk|Wv] (B,S,3072)

// bf16 split buffers
__device__ __nv_bfloat16 g_x_hi[BSZ * SEQ * EMB];
__device__ __nv_bfloat16 g_x_lo[BSZ * SEQ * EMB];
__device__ __nv_bfloat16 g_a_hi[BSZ * SEQ * EMB];   // attn out hi (B,S,H,D)
__device__ __nv_bfloat16 g_a_lo[BSZ * SEQ * EMB];   // attn out lo
__device__ __nv_bfloat16 g_qh[BSZ * SEQ * EMB];     // rope'd q hi (B,H,S,D)
__device__ __nv_bfloat16 g_ql[BSZ * SEQ * EMB];
__device__ __nv_bfloat16 g_kh[BSZ * SEQ * KVD];     // rope'd k hi (B,KV,S,D)
__device__ __nv_bfloat16 g_kl[BSZ * SEQ * KVD];
__device__ __nv_bfloat16 g_vh[BSZ * SEQ * KVD];     // v hi (B,KV,S,D)
__device__ __nv_bfloat16 g_vl[BSZ * SEQ * KVD];
__device__ __nv_bfloat16 g_wqkv_h[QKVN * EMB];      // packed [Wq;Wk;Wv]^T hi
__device__ __nv_bfloat16 g_wqkv_l[QKVN * EMB];
__device__ __nv_bfloat16 g_wo_h[EMB * EMB];
__device__ __nv_bfloat16 g_wo_l[EMB * EMB];

// ======================= helpers =============================================
__device__ __forceinline__ uint32_t cvta_smem(const void* p) {
    uint32_t a;
    asm("{ .reg .u64 t; cvta.to.shared.u64 t, %1; cvt.u32.u64 %0, t; }"
        : "=r"(a) : "l"(p));
    return a;
}

__device__ __forceinline__ void cp16(uint32_t dst, const void* src) {
    asm volatile("cp.async.cg.shared.global [%0], [%1], 16;"
                 :: "r"(dst), "l"(src) : "memory");
}
#define CP_COMMIT() asm volatile("cp.async.commit_group;" ::: "memory")
#define CP_WAIT(n)  asm volatile("cp.async.wait_group %0;" :: "n"(n) : "memory")

__device__ __forceinline__ void ldsm_x4(uint32_t& r0, uint32_t& r1,
                                        uint32_t& r2, uint32_t& r3, uint32_t addr) {
    asm volatile("ldmatrix.sync.aligned.m8n8.x4.shared.b16 {%0,%1,%2,%3}, [%4];"
                 : "=r"(r0), "=r"(r1), "=r"(r2), "=r"(r3) : "r"(addr));
}

__device__ __forceinline__ void ldsm_x4_t(uint32_t& r0, uint32_t& r1,
                                          uint32_t& r2, uint32_t& r3, uint32_t addr) {
    asm volatile("ldmatrix.sync.aligned.m8n8.x4.trans.shared.b16 {%0,%1,%2,%3}, [%4];"
                 : "=r"(r0), "=r"(r1), "=r"(r2), "=r"(r3) : "r"(addr));
}

__device__ __forceinline__ void mma_bf16(float& d0, float& d1, float& d2, float& d3,
                                         uint32_t a0, uint32_t a1, uint32_t a2, uint32_t a3,
                                         uint32_t b0, uint32_t b1) {
    asm volatile(
        "mma.sync.aligned.m16n8k16.row.col.f32.bf16.bf16.f32 "
        "{%0,%1,%2,%3}, {%4,%5,%6,%7}, {%8,%9}, {%0,%1,%2,%3};"
        : "+f"(d0), "+f"(d1), "+f"(d2), "+f"(d3)
        : "r"(a0), "r"(a1), "r"(a2), "r"(a3), "r"(b0), "r"(b1));
}

__device__ __forceinline__ uint32_t pack_bf16(float a, float b) {
    __nv_bfloat162 t(__float2bfloat16(a), __float2bfloat16(b));
    return *(uint32_t*)&t;
}

// ============ split conversion: fp32 -> (hi bf16, lo bf16) ===================
__global__ void split_kernel(const float4* __restrict__ in,
                             __nv_bfloat16* __restrict__ hi,
                             __nv_bfloat16* __restrict__ lo)
{
    int i = blockIdx.x * blockDim.x + threadIdx.x;
    float4 v = in[i];
    __nv_bfloat16 h[4], l[4];
    h[0] = __float2bfloat16(v.x); l[0] = __float2bfloat16(v.x - __bfloat162float(h[0]));
    h[1] = __float2bfloat16(v.y); l[1] = __float2bfloat16(v.y - __bfloat162float(h[1]));
    h[2] = __float2bfloat16(v.z); l[2] = __float2bfloat16(v.z - __bfloat162float(h[2]));
    h[3] = __float2bfloat16(v.w); l[3] = __float2bfloat16(v.w - __bfloat162float(h[3]));
    *(uint2*)&hi[(size_t)i * 4] = *(uint2*)h;
    *(uint2*)&lo[(size_t)i * 4] = *(uint2*)l;
}

// ===== weight transpose + split: W[K,N] fp32 -> Wt_hi/lo [N,K] bf16 ==========
__global__ void wsplit_t_kernel(const float* __restrict__ W,
                                __nv_bfloat16* __restrict__ Th,
                                __nv_bfloat16* __restrict__ Tl,
                                int K, int N)
{
    __shared__ float tile[32][33];
    int n0 = blockIdx.x * 32, k0 = blockIdx.y * 32;
    int tx = threadIdx.x, ty = threadIdx.y;   // 32 x 8
#pragma unroll
    for (int i = 0; i < 4; i++)
        tile[ty + 8 * i][tx] = W[(size_t)(k0 + ty + 8 * i) * N + n0 + tx];
    __syncthreads();
#pragma unroll
    for (int i = 0; i < 4; i++) {
        float v = tile[tx][ty + 8 * i];
        __nv_bfloat16 h = __float2bfloat16(v);
        __nv_bfloat16 l = __float2bfloat16(v - __bfloat162float(h));
        size_t o = (size_t)(n0 + ty + 8 * i) * K + k0 + tx;
        Th[o] = h;
        Tl[o] = l;
    }
}

// ====== mma.sync GEMM: C[M,N] = A[M,K] @ W[K,N], 3-term bf16 split ===========
// cp.async 2-stage pipeline, BK=64. CTA 128x128, 256 threads (2x4 warps).
// smem pitch 144 B/row: 16B bank-shift per row -> conflict-free ldmatrix.
#define ROWB 144
#define TILE_SB (128 * ROWB)        // 18432
#define STAGE_SB (4 * TILE_SB)      // 73728

__global__ void __launch_bounds__(256) gemm_mma_kernel(
    const __nv_bfloat16* __restrict__ Ah, const __nv_bfloat16* __restrict__ Al,
    const __nv_bfloat16* __restrict__ Bh, const __nv_bfloat16* __restrict__ Bl,
    float* __restrict__ C, int M, int N, int K)
{
    extern __shared__ char dsm[];
    const int tid = threadIdx.x;
    const int wid = tid >> 5, lane = tid & 31;
    const int wm = wid >> 2, wn = wid & 3;
    const int mT = blockIdx.y, nT = blockIdx.x;

    const uint32_t sbase = cvta_smem(dsm);

    // per thread per tile: one row-half (64 B = 4 cp16)
    const int gr = tid >> 1;
    const int gh = tid & 1;
    const __nv_bfloat16* srcs[4] = {
        Ah + (size_t)(mT * 128 + gr) * K + gh * 32,
        Al + (size_t)(mT * 128 + gr) * K + gh * 32,
        Bh + (size_t)(nT * 128 + gr) * K + gh * 32,
        Bl + (size_t)(nT * 128 + gr) * K + gh * 32
    };
    const uint32_t sdst = gr * ROWB + gh * 64;

    float acc[4][4][4];
#pragma unroll
    for (int i = 0; i < 4; i++)
#pragma unroll
        for (int j = 0; j < 4; j++)
#pragma unroll
            for (int v = 0; v < 4; v++) acc[i][j][v] = 0.f;

    const int l8 = lane & 7, mi = lane >> 3;
    const uint32_t a_off = (uint32_t)(wm * 64 + l8 + ((mi & 1) << 3)) * ROWB
                         + ((mi >> 1) << 4);
    const uint32_t b_off = (uint32_t)(wn * 32 + l8 + ((mi & 1) << 3)) * ROWB
                         + ((mi >> 1) << 4);

    const int nch = K >> 6;   // BK = 64

    // prologue: async-load stage 0
#pragma unroll
    for (int t = 0; t < 4; t++) {
        uint32_t a = sbase + t * TILE_SB + sdst;
#pragma unroll
        for (int q = 0; q < 4; q++) cp16(a + q * 16, srcs[t] + q * 8);
    }
    CP_COMMIT();

    for (int ch = 0; ch < nch; ch++) {
        const uint32_t stage = sbase + (ch & 1) * STAGE_SB;
        const bool more = (ch + 1 < nch);

        if (more) {
            const int k0 = (ch + 1) << 6;
            const uint32_t nstage = sbase + ((ch + 1) & 1) * STAGE_SB;
#pragma unroll
            for (int t = 0; t < 4; t++) {
                uint32_t a = nstage + t * TILE_SB + sdst;
#pragma unroll
                for (int q = 0; q < 4; q++) cp16(a + q * 16, srcs[t] + k0 + q * 8);
            }
            CP_COMMIT();
            CP_WAIT(1);           // stage ch is complete
        } else {
            CP_WAIT(0);
        }
        __syncthreads();

#pragma unroll
        for (int k16 = 0; k16 < 4; k16++) {
            const uint32_t kb = k16 * 32;
            uint32_t ah[4][4], al[4][4];
#pragma unroll
            for (int i = 0; i < 4; i++) {
                uint32_t addr = stage + a_off + (uint32_t)(i * 16) * ROWB + kb;
                ldsm_x4(ah[i][0], ah[i][1], ah[i][2], ah[i][3], addr);
                ldsm_x4(al[i][0], al[i][1], al[i][2], al[i][3], addr + TILE_SB);
            }
            uint32_t bh[4][2], bl[4][2];
#pragma unroll
            for (int p = 0; p < 2; p++) {
                uint32_t addr = stage + 2 * TILE_SB + b_off + (uint32_t)(p * 16) * ROWB + kb;
                uint32_t r0, r1, r2, r3;
                ldsm_x4(r0, r1, r2, r3, addr);
                bh[2 * p][0] = r0; bh[2 * p][1] = r2;
                bh[2 * p + 1][0] = r1; bh[2 * p + 1][1] = r3;
                ldsm_x4(r0, r1, r2, r3, addr + TILE_SB);
                bl[2 * p][0] = r0; bl[2 * p][1] = r2;
                bl[2 * p + 1][0] = r1; bl[2 * p + 1][1] = r3;
            }
#pragma unroll
            for (int i = 0; i < 4; i++)
#pragma unroll
                for (int j = 0; j < 4; j++) {
                    float* d = acc[i][j];
                    mma_bf16(d[0], d[1], d[2], d[3],
                             ah[i][0], ah[i][1], ah[i][2], ah[i][3],
                             bh[j][0], bh[j][1]);
                    mma_bf16(d[0], d[1], d[2], d[3],
                             ah[i][0], ah[i][1], ah[i][2], ah[i][3],
                             bl[j][0], bl[j][1]);
                    mma_bf16(d[0], d[1], d[2], d[3],
                             al[i][0], al[i][1], al[i][2], al[i][3],
                             bh[j][0], bh[j][1]);
                }
        }
        __syncthreads();   // all warps done reading before buffer is overwritten
    }

    const int er = lane >> 2, ec = (lane & 3) * 2;
    float* Cb = C + (size_t)(mT * 128 + wm * 64 + er) * N + nT * 128 + wn * 32 + ec;
#pragma unroll
    for (int i = 0; i < 4; i++)
#pragma unroll
        for (int j = 0; j < 4; j++) {
            float* p0 = Cb + (size_t)(i * 16) * N + j * 8;
            *(float2*)p0                      = make_float2(acc[i][j][0], acc[i][j][1]);
            *(float2*)(p0 + (size_t)8 * N)    = make_float2(acc[i][j][2], acc[i][j][3]);
        }
}

// -------- RoPE q: qkv (B,S,3072) fp32 -> (B,H,S,D) bf16 hi/lo ---------------
__global__ void rope_q_kernel(const float* __restrict__ qkv,
                              __nv_bfloat16* __restrict__ qh,
                              __nv_bfloat16* __restrict__ ql,
                              const float* __restrict__ cosT, const float* __restrict__ sinT)
{
    int idx = blockIdx.x * blockDim.x + threadIdx.x;
    int d = idx & 31;
    int h = (idx >> 5) & 31;
    int s = (idx >> 10) & 2047;
    int b = idx >> 21;
    float cv = cosT[s * HD + d];
    float sv = sinT[s * HD + d];
    size_t i0 = (size_t)(b * SEQ + s) * QKVN + h * HD + d;
    float x1 = qkv[i0], x2 = qkv[i0 + 32];
    float v1 = x1 * cv - x2 * sv;
    float v2 = x2 * cv + x1 * sv;
    size_t o0 = ((size_t)(b * NH + h) * SEQ + s) * HD + d;
    __nv_bfloat16 h1 = __float2bfloat16(v1);
    __nv_bfloat16 h2 = __float2bfloat16(v2);
    qh[o0]      = h1;
    qh[o0 + 32] = h2;
    ql[o0]      = __float2bfloat16(v1 - __bfloat162float(h1));
    ql[o0 + 32] = __float2bfloat16(v2 - __bfloat162float(h2));
}

// ---- RoPE k: qkv (B,S,3072) -> fp32 next_k + bf16 hi/lo (B,KV,S,D) ---------
__global__ void rope_k_kernel(const float* __restrict__ qkv, float* __restrict__ kout,
                              __nv_bfloat16* __restrict__ kh,
                              __nv_bfloat16* __restrict__ kl,
                              const float* __restrict__ cosT, const float* __restrict__ sinT)
{
    int idx = blockIdx.x * blockDim.x + threadIdx.x;
    int d = idx & 31;
    int h = (idx >> 5) & 7;
    int s = (idx >> 8) & 2047;
    int b = idx >> 19;
    float cv = cosT[s * HD + d];
    float sv = sinT[s * HD + d];
    size_t i0 = (size_t)(b * SEQ + s) * QKVN + EMB + h * HD + d;
    float x1 = qkv[i0], x2 = qkv[i0 + 32];
    float v1 = x1 * cv - x2 * sv;
    float v2 = x2 * cv + x1 * sv;
    size_t o0 = ((size_t)(b * NKV + h) * SEQ + s) * HD + d;
    kout[o0]      = v1;
    kout[o0 + 32] = v2;
    __nv_bfloat16 h1 = __float2bfloat16(v1);
    __nv_bfloat16 h2 = __float2bfloat16(v2);
    kh[o0]      = h1;
    kh[o0 + 32] = h2;
    kl[o0]      = __float2bfloat16(v1 - __bfloat162float(h1));
    kl[o0 + 32] = __float2bfloat16(v2 - __bfloat162float(h2));
}

// -- V transpose: qkv (B,S,3072) -> fp32 next_v + bf16 hi/lo (B,KV,S,D) ------
__global__ void vtrans_kernel(const float4* __restrict__ qkv4, float4* __restrict__ vout,
                              __nv_bfloat16* __restrict__ vh,
                              __nv_bfloat16* __restrict__ vl)
{
    int idx = blockIdx.x * blockDim.x + threadIdx.x;
    int f = idx & 15;
    int h = (idx >> 4) & 7;
    int s = (idx >> 7) & 2047;
    int b = idx >> 18;
    float4 v = qkv4[(size_t)(b * SEQ + s) * (QKVN / 4) + (EMB + KVD) / 4 + h * 16 + f];
    size_t o = ((size_t)(b * NKV + h) * SEQ + s) * (HD / 4) + f;
    vout[o] = v;
    __nv_bfloat16 hh[4], ll[4];
    hh[0] = __float2bfloat16(v.x); ll[0] = __float2bfloat16(v.x - __bfloat162float(hh[0]));
    hh[1] = __float2bfloat16(v.y); ll[1] = __float2bfloat16(v.y - __bfloat162float(hh[1]));
    hh[2] = __float2bfloat16(v.z); ll[2] = __float2bfloat16(v.z - __bfloat162float(hh[2]));
    hh[3] = __float2bfloat16(v.w); ll[3] = __float2bfloat16(v.w - __bfloat162float(hh[3]));
    *(uint2*)&vh[o * 4] = *(uint2*)hh;
    *(uint2*)&vl[o * 4] = *(uint2*)ll;
}

// ---------------- causal flash attention (mma.sync bf16 split) ---------------
#define FROWB  144
#define FTILE  (64 * FROWB)
#define FSMEM  (6 * FTILE)

__global__ void __launch_bounds__(128) flash_mma_kernel(
    const __nv_bfloat16* __restrict__ Qh, const __nv_bfloat16* __restrict__ Ql,
    const __nv_bfloat16* __restrict__ Kh, const __nv_bfloat16* __restrict__ Kl,
    const __nv_bfloat16* __restrict__ Vh, const __nv_bfloat16* __restrict__ Vl,
    __nv_bfloat16* __restrict__ Oh, __nv_bfloat16* __restrict__ Ol)
{
    extern __shared__ char fsm[];
    const uint32_t sb  = cvta_smem(fsm);
    const uint32_t sQh = sb, sQl = sb + FTILE;
    const uint32_t sKh = sb + 2 * FTILE, sKl = sb + 3 * FTILE;
    const uint32_t sVh = sb + 4 * FTILE, sVl = sb + 5 * FTILE;

    const int qt = blockIdx.x, hh = blockIdx.y;
    const int b = hh >> 5, h = hh & 31, kvh = h >> 2;
    const int tid = threadIdx.x, wid = tid >> 5, lane = tid & 31;

    const __nv_bfloat16* Qhb = Qh + ((size_t)((b * NH + h) * SEQ) + qt * 64) * HD;
    const __nv_bfloat16* Qlb = Ql + ((size_t)((b * NH + h) * SEQ) + qt * 64) * HD;
    const __nv_bfloat16* Khb = Kh + (size_t)((b * NKV + kvh) * SEQ) * HD;
    const __nv_bfloat16* Klb = Kl + (size_t)((b * NKV + kvh) * SEQ) * HD;
    const __nv_bfloat16* Vhb = Vh + (size_t)((b * NKV + kvh) * SEQ) * HD;
    const __nv_bfloat16* Vlb = Vl + (size_t)((b * NKV + kvh) * SEQ) * HD;

    {
        const int r = tid >> 1, hf = tid & 1;
        const uint4* s0 = (const uint4*)(Qhb + (size_t)r * HD + hf * 32);
        const uint4* s1 = (const uint4*)(Qlb + (size_t)r * HD + hf * 32);
        uint32_t d0 = sQh + r * FROWB + hf * 64;
        uint32_t d1 = sQl + r * FROWB + hf * 64;
#pragma unroll
        for (int i = 0; i < 4; i++) {
            uint4 v = s0[i];
            asm volatile("st.shared.v4.b32 [%0], {%1,%2,%3,%4};"
                         :: "r"(d0 + i * 16), "r"(v.x), "r"(v.y), "r"(v.z), "r"(v.w) : "memory");
            v = s1[i];
            asm volatile("st.shared.v4.b32 [%0], {%1,%2,%3,%4};"
                         :: "r"(d1 + i * 16), "r"(v.x), "r"(v.y), "r"(v.z), "r"(v.w) : "memory");
        }
    }

    const int l8 = lane & 7, mi = lane >> 3;
    const uint32_t qa_off = (uint32_t)(wid * 16 + l8 + ((mi & 1) << 3)) * FROWB
                          + ((mi >> 1) << 4);
    const uint32_t kb_base = (uint32_t)(l8 + ((mi & 1) << 3)) * FROWB + ((mi >> 1) << 4);
    const uint32_t vb_base = (uint32_t)(((mi & 1) << 3) + l8) * FROWB + ((mi >> 1) << 4);

    float m0 = -1e30f, m1 = -1e30f, l0 = 0.f, l1 = 0.f;
    float o[8][4];
#pragma unroll
    for (int j = 0; j < 8; j++)
#pragma unroll
        for (int v = 0; v < 4; v++) o[j][v] = 0.f;

    const int ntiles = qt + 1;
    for (int kt = 0; kt < ntiles; kt++) {
        __syncthreads();
        {
            const int r = tid >> 1, hf = tid & 1;
            const size_t goff = (size_t)(kt * 64 + r) * HD + hf * 32;
            const uint4* s0 = (const uint4*)(Khb + goff);
            const uint4* s1 = (const uint4*)(Klb + goff);
            const uint4* s2 = (const uint4*)(Vhb + goff);
            const uint4* s3 = (const uint4*)(Vlb + goff);
            const uint32_t dof = r * FROWB + hf * 64;
#pragma unroll
            for (int i = 0; i < 4; i++) {
                uint4 v = s0[i];
                asm volatile("st.shared.v4.b32 [%0], {%1,%2,%3,%4};"
                             :: "r"(sKh + dof + i * 16), "r"(v.x), "r"(v.y), "r"(v.z), "r"(v.w) : "memory");
                v = s1[i];
                asm volatile("st.shared.v4.b32 [%0], {%1,%2,%3,%4};"
                             :: "r"(sKl + dof + i * 16), "r"(v.x), "r"(v.y), "r"(v.z), "r"(v.w) : "memory");
                v = s2[i];
                asm volatile("st.shared.v4.b32 [%0], {%1,%2,%3,%4};"
                             :: "r"(sVh + dof + i * 16), "r"(v.x), "r"(v.y), "r"(v.z), "r"(v.w) : "memory");
                v = s3[i];
                asm volatile("st.shared.v4.b32 [%0], {%1,%2,%3,%4};"
                             :: "r"(sVl + dof + i * 16), "r"(v.x), "r"(v.y), "r"(v.z), "r"(v.w) : "memory");
            }
        }
        __syncthreads();

        float sa[8][4];
#pragma unroll
        for (int j = 0; j < 8; j++)
#pragma unroll
            for (int v = 0; v < 4; v++) sa[j][v] = 0.f;

#pragma unroll
        for (int ks = 0; ks < 4; ks++) {
            uint32_t aqh[4], aql[4];
            ldsm_x4(aqh[0], aqh[1], aqh[2], aqh[3], sQh + qa_off + ks * 32);
            ldsm_x4(aql[0], aql[1], aql[2], aql[3], sQl + qa_off + ks * 32);
#pragma unroll
            for (int p = 0; p < 4; p++) {
                uint32_t addr = kb_base + (uint32_t)(p * 16) * FROWB + ks * 32;
                uint32_t r0, r1, r2, r3;
                uint32_t bh0[2], bh1[2], bl0[2], bl1[2];
                ldsm_x4(r0, r1, r2, r3, sKh + addr);
                bh0[0] = r0; bh0[1] = r2; bh1[0] = r1; bh1[1] = r3;
                ldsm_x4(r0, r1, r2, r3, sKl + addr);
                bl0[0] = r0; bl0[1] = r2; bl1[0] = r1; bl1[1] = r3;
                float* d0 = sa[2 * p];
                float* d1 = sa[2 * p + 1];
                mma_bf16(d0[0], d0[1], d0[2], d0[3], aqh[0], aqh[1], aqh[2], aqh[3], bh0[0], bh0[1]);
                mma_bf16(d0[0], d0[1], d0[2], d0[3], aqh[0], aqh[1], aqh[2], aqh[3], bl0[0], bl0[1]);
                mma_bf16(d0[0], d0[1], d0[2], d0[3], aql[0], aql[1], aql[2], aql[3], bh0[0], bh0[1]);
                mma_bf16(d1[0], d1[1], d1[2], d1[3], aqh[0], aqh[1], aqh[2], aqh[3], bh1[0], bh1[1]);
                mma_bf16(d1[0], d1[1], d1[2], d1[3], aqh[0], aqh[1], aqh[2], aqh[3], bl1[0], bl1[1]);
                mma_bf16(d1[0], d1[1], d1[2], d1[3], aql[0], aql[1], aql[2], aql[3], bh1[0], bh1[1]);
            }
        }

        const bool diag = (kt == qt);
        const int rlo = wid * 16 + (lane >> 2);
        const int rhi = rlo + 8;
        float mx0 = -1e30f, mx1 = -1e30f;
#pragma unroll
        for (int j = 0; j < 8; j++) {
            const int c0 = 8 * j + (lane & 3) * 2;
#pragma unroll
            for (int v = 0; v < 4; v++) {
                float sc = sa[j][v] * 0.125f;
                if (diag) {
                    int col = c0 + (v & 1);
                    int row = (v < 2) ? rlo : rhi;
                    if (col > row) sc = -1e30f;
                }
                sa[j][v] = sc;
            }
            mx0 = fmaxf(mx0, fmaxf(sa[j][0], sa[j][1]));
            mx1 = fmaxf(mx1, fmaxf(sa[j][2], sa[j][3]));
        }
        mx0 = fmaxf(mx0, __shfl_xor_sync(0xffffffffu, mx0, 1));
        mx0 = fmaxf(mx0, __shfl_xor_sync(0xffffffffu, mx0, 2));
        mx1 = fmaxf(mx1, __shfl_xor_sync(0xffffffffu, mx1, 1));
        mx1 = fmaxf(mx1, __shfl_xor_sync(0xffffffffu, mx1, 2));

        const float mn0 = fmaxf(m0, mx0), mn1 = fmaxf(m1, mx1);
        const float al0 = __expf(m0 - mn0), al1 = __expf(m1 - mn1);
        m0 = mn0; m1 = mn1;

        float sum0 = 0.f, sum1 = 0.f;
#pragma unroll
        for (int j = 0; j < 8; j++) {
            float e0 = __expf(sa[j][0] - mn0);
            float e1 = __expf(sa[j][1] - mn0);
            float e2 = __expf(sa[j][2] - mn1);
            float e3 = __expf(sa[j][3] - mn1);
            sa[j][0] = e0; sa[j][1] = e1; sa[j][2] = e2; sa[j][3] = e3;
            sum0 += e0 + e1;
            sum1 += e2 + e3;
        }
        sum0 += __shfl_xor_sync(0xffffffffu, sum0, 1);
        sum0 += __shfl_xor_sync(0xffffffffu, sum0, 2);
        sum1 += __shfl_xor_sync(0xffffffffu, sum1, 1);
        sum1 += __shfl_xor_sync(0xffffffffu, sum1, 2);
        l0 = l0 * al0 + sum0;
        l1 = l1 * al1 + sum1;

#pragma unroll
        for (int j = 0; j < 8; j++) {
            o[j][0] *= al0; o[j][1] *= al0;
            o[j][2] *= al1; o[j][3] *= al1;
        }

#pragma unroll
        for (int kc = 0; kc < 4; kc++) {
            const float* e0 = sa[2 * kc];
            const float* e1 = sa[2 * kc + 1];
            uint32_t ph[4], pl[4];
            ph[0] = pack_bf16(e0[0], e0[1]);
            ph[1] = pack_bf16(e0[2], e0[3]);
            ph[2] = pack_bf16(e1[0], e1[1]);
            ph[3] = pack_bf16(e1[2], e1[3]);
            {
                __nv_bfloat162 t;
                t = *(__nv_bfloat162*)&ph[0];
                pl[0] = pack_bf16(e0[0] - __bfloat162float(t.x), e0[1] - __bfloat162float(t.y));
                t = *(__nv_bfloat162*)&ph[1];
                pl[1] = pack_bf16(e0[2] - __bfloat162float(t.x), e0[3] - __bfloat162float(t.y));
                t = *(__nv_bfloat162*)&ph[2];
                pl[2] = pack_bf16(e1[0] - __bfloat162float(t.x), e1[1] - __bfloat162float(t.y));
                t = *(__nv_bfloat162*)&ph[3];
                pl[3] = pack_bf16(e1[2] - __bfloat162float(t.x), e1[3] - __bfloat162float(t.y));
            }
#pragma unroll
            for (int t4 = 0; t4 < 4; t4++) {
                uint32_t addr = vb_base + (uint32_t)(kc * 16) * FROWB + t4 * 32;
                uint32_t r0, r1, r2, r3;
                uint32_t bh0[2], bh1[2], bl0[2], bl1[2];
                ldsm_x4_t(r0, r1, r2, r3, sVh + addr);
                bh0[0] = r0; bh0[1] = r1; bh1[0] = r2; bh1[1] = r3;
                ldsm_x4_t(r0, r1, r2, r3, sVl + addr);
                bl0[0] = r0; bl0[1] = r1; bl1[0] = r2; bl1[1] = r3;
                float* d0 = o[2 * t4];
                float* d1 = o[2 * t4 + 1];
                mma_bf16(d0[0], d0[1], d0[2], d0[3], ph[0], ph[1], ph[2], ph[3], bh0[0], bh0[1]);
                mma_bf16(d0[0], d0[1], d0[2], d0[3], pl[0], pl[1], pl[2], pl[3], bh0[0], bh0[1]);
                mma_bf16(d0[0], d0[1], d0[2], d0[3], ph[0], ph[1], ph[2], ph[3], bl0[0], bl0[1]);
                mma_bf16(d1[0], d1[1], d1[2], d1[3], ph[0], ph[1], ph[2], ph[3], bh1[0], bh1[1]);
                mma_bf16(d1[0], d1[1], d1[2], d1[3], pl[0], pl[1], pl[2], pl[3], bh1[0], bh1[1]);
                mma_bf16(d1[0], d1[1], d1[2], d1[3], ph[0], ph[1], ph[2], ph[3], bl1[0], bl1[1]);
            }
        }
    }

    const float inv0 = 1.f / l0, inv1 = 1.f / l1;
    const int rlo = qt * 64 + wid * 16 + (lane >> 2);
    const int rhi = rlo + 8;
#pragma unroll
    for (int j = 0; j < 8; j++) {
        const int d = 8 * j + (lane & 3) * 2;
        size_t plo = ((size_t)(b * SEQ + rlo) * NH + h) * HD + d;
        size_t phi = ((size_t)(b * SEQ + rhi) * NH + h) * HD + d;
        float v0 = o[j][0] * inv0, v1 = o[j][1] * inv0;
        float v2 = o[j][2] * inv1, v3 = o[j][3] * inv1;
        uint32_t h01 = pack_bf16(v0, v1);
        uint32_t h23 = pack_bf16(v2, v3);
        __nv_bfloat162 th;
        th = *(__nv_bfloat162*)&h01;
        uint32_t l01 = pack_bf16(v0 - __bfloat162float(th.x), v1 - __bfloat162float(th.y));
        th = *(__nv_bfloat162*)&h23;
        uint32_t l23 = pack_bf16(v2 - __bfloat162float(th.x), v3 - __bfloat162float(th.y));
        *(uint32_t*)&Oh[plo] = h01;
        *(uint32_t*)&Ol[plo] = l01;
        *(uint32_t*)&Oh[phi] = h23;
        *(uint32_t*)&Ol[phi] = l23;
    }
}

// ---------------- launch -----------------------------------------------------
extern "C" void kernel_launch(void* const* d_in, const int* in_sizes, int n_in,
                              void* d_out, int out_size)
{
    const float* x    = (const float*)d_in[0];
    const float* cosT = (const float*)d_in[2];
    const float* sinT = (const float*)d_in[3];
    const float* Wq   = (const float*)d_in[4];
    const float* Wk   = (const float*)d_in[5];
    const float* Wv   = (const float*)d_in[6];
    const float* Wo   = (const float*)d_in[7];

    float* out = (float*)d_out;                         // (B,S,E)
    float* nk  = out + (size_t)BSZ * SEQ * EMB;         // (B,KV,S,D)
    float* nv  = nk + (size_t)BSZ * NKV * SEQ * HD;     // (B,KV,S,D)

    float* qkv_lin;
    cudaGetSymbolAddress((void**)&qkv_lin, g_qkv_lin);

    __nv_bfloat16 *xh, *xl, *ah, *al, *qh, *ql, *kh, *kl, *vh, *vl;
    __nv_bfloat16 *wqkvh, *wqkvl, *woh, *wol;
    cudaGetSymbolAddress((void**)&xh,  g_x_hi);
    cudaGetSymbolAddress((void**)&xl,  g_x_lo);
    cudaGetSymbolAddress((void**)&ah,  g_a_hi);
    cudaGetSymbolAddress((void**)&al,  g_a_lo);
    cudaGetSymbolAddress((void**)&qh,  g_qh);
    cudaGetSymbolAddress((void**)&ql,  g_ql);
    cudaGetSymbolAddress((void**)&kh,  g_kh);
    cudaGetSymbolAddress((void**)&kl,  g_kl);
    cudaGetSymbolAddress((void**)&vh,  g_vh);
    cudaGetSymbolAddress((void**)&vl,  g_vl);
    cudaGetSymbolAddress((void**)&wqkvh, g_wqkv_h);
    cudaGetSymbolAddress((void**)&wqkvl, g_wqkv_l);
    cudaGetSymbolAddress((void**)&woh, g_wo_h);
    cudaGetSymbolAddress((void**)&wol, g_wo_l);

    cudaFuncSetAttribute(gemm_mma_kernel,
                         cudaFuncAttributeMaxDynamicSharedMemorySize, 2 * STAGE_SB);
    cudaFuncSetAttribute(flash_mma_kernel,
                         cudaFuncAttributeMaxDynamicSharedMemorySize, FSMEM);

    const int M = BSZ * SEQ;          // 4096
    const size_t NX = (size_t)M * EMB;

    // split x + weights (transpose+split; QKV packed row-wise [3072 x 2048])
    split_kernel<<<(int)(NX / 4 / 256), 256>>>((const float4*)x, xh, xl);
    wsplit_t_kernel<<<dim3(EMB / 32, EMB / 32), dim3(32, 8)>>>(Wq, wqkvh, wqkvl, EMB, EMB);
    wsplit_t_kernel<<<dim3(KVD / 32, EMB / 32), dim3(32, 8)>>>(
        Wk, wqkvh + (size_t)EMB * EMB, wqkvl + (size_t)EMB * EMB, EMB, KVD);
    wsplit_t_kernel<<<dim3(KVD / 32, EMB / 32), dim3(32, 8)>>>(
        Wv, wqkvh + (size_t)(EMB + KVD) * EMB, wqkvl + (size_t)(EMB + KVD) * EMB, EMB, KVD);
    wsplit_t_kernel<<<dim3(EMB / 32, EMB / 32), dim3(32, 8)>>>(Wo, woh, wol, EMB, EMB);

    // fused QKV projection on tensor cores
    gemm_mma_kernel<<<dim3(QKVN / 128, M / 128), 256, 2 * STAGE_SB>>>(
        xh, xl, wqkvh, wqkvl, qkv_lin, M, QKVN, EMB);

    // rope + layout transforms (fp32 k/v land in d_out; bf16 splits for attn)
    rope_q_kernel<<<(BSZ * SEQ * NH * 32) / 256, 256>>>(qkv_lin, qh, ql, cosT, sinT);
    rope_k_kernel<<<(BSZ * SEQ * NKV * 32) / 256, 256>>>(qkv_lin, nk, kh, kl, cosT, sinT);
    vtrans_kernel<<<(BSZ * SEQ * NKV * 16) / 256, 256>>>(
        (const float4*)qkv_lin, (float4*)nv, vh, vl);

    // attention on tensor cores (writes hi/lo split directly)
    flash_mma_kernel<<<dim3(SEQ / 64, BSZ * NH), 128, FSMEM>>>(
        qh, ql, kh, kl, vh, vl, ah, al);

    // output projection on tensor cores
    gemm_mma_kernel<<<dim3(EMB / 128, M / 128), 256, 2 * STAGE_SB>>>(
        ah, al, woh, wol, out, M, EMB, EMB);
}

// round 11
// speedup vs baseline: 1.1744x; 1.1744x over previous
#include <cuda_runtime.h>
#include <cuda_bf16.h>
#include <math.h>
#include <stdint.h>

#define BSZ 2
#define SEQ 2048
#define EMB 2048
#define NH  32
#define NKV 8
#define HD  64
#define KVD (NKV * HD)   // 512
#define QKVN (EMB + 2 * KVD)   // 3072

// ---------------- scratch (static device memory; no allocs allowed) ----------
__device__ float g_qkv_lin[BSZ * SEQ * QKVN];       // x@[Wq|Wk|Wv] (B,S,3072)

// bf16 split buffers
__device__ __nv_bfloat16 g_x_hi[BSZ * SEQ * EMB];
__device__ __nv_bfloat16 g_x_lo[BSZ * SEQ * EMB];
__device__ __nv_bfloat16 g_a_hi[BSZ * SEQ * EMB];   // attn out hi (B,S,H,D)
__device__ __nv_bfloat16 g_a_lo[BSZ * SEQ * EMB];   // attn out lo
__device__ __nv_bfloat16 g_qh[BSZ * SEQ * EMB];     // rope'd q hi (B,H,S,D)
__device__ __nv_bfloat16 g_ql[BSZ * SEQ * EMB];
__device__ __nv_bfloat16 g_kh[BSZ * SEQ * KVD];     // rope'd k hi (B,KV,S,D)
__device__ __nv_bfloat16 g_kl[BSZ * SEQ * KVD];
__device__ __nv_bfloat16 g_vh[BSZ * SEQ * KVD];     // v hi (B,KV,S,D)
__device__ __nv_bfloat16 g_vl[BSZ * SEQ * KVD];
__device__ __nv_bfloat16 g_wqkv_h[QKVN * EMB];      // packed [Wq;Wk;Wv]^T hi
__device__ __nv_bfloat16 g_wqkv_l[QKVN * EMB];
__device__ __nv_bfloat16 g_wo_h[EMB * EMB];
__device__ __nv_bfloat16 g_wo_l[EMB * EMB];

// ======================= helpers =============================================
__device__ __forceinline__ uint32_t cvta_smem(const void* p) {
    uint32_t a;
    asm("{ .reg .u64 t; cvta.to.shared.u64 t, %1; cvt.u32.u64 %0, t; }"
        : "=r"(a) : "l"(p));
    return a;
}

__device__ __forceinline__ void cp16(uint32_t dst, const void* src) {
    asm volatile("cp.async.cg.shared.global [%0], [%1], 16;"
                 :: "r"(dst), "l"(src) : "memory");
}
#define CP_COMMIT() asm volatile("cp.async.commit_group;" ::: "memory")
#define CP_WAIT(n)  asm volatile("cp.async.wait_group %0;" :: "n"(n) : "memory")

__device__ __forceinline__ void ldsm_x4(uint32_t& r0, uint32_t& r1,
                                        uint32_t& r2, uint32_t& r3, uint32_t addr) {
    asm volatile("ldmatrix.sync.aligned.m8n8.x4.shared.b16 {%0,%1,%2,%3}, [%4];"
                 : "=r"(r0), "=r"(r1), "=r"(r2), "=r"(r3) : "r"(addr));
}

__device__ __forceinline__ void ldsm_x4_t(uint32_t& r0, uint32_t& r1,
                                          uint32_t& r2, uint32_t& r3, uint32_t addr) {
    asm volatile("ldmatrix.sync.aligned.m8n8.x4.trans.shared.b16 {%0,%1,%2,%3}, [%4];"
                 : "=r"(r0), "=r"(r1), "=r"(r2), "=r"(r3) : "r"(addr));
}

__device__ __forceinline__ void mma_bf16(float& d0, float& d1, float& d2, float& d3,
                                         uint32_t a0, uint32_t a1, uint32_t a2, uint32_t a3,
                                         uint32_t b0, uint32_t b1) {
    asm volatile(
        "mma.sync.aligned.m16n8k16.row.col.f32.bf16.bf16.f32 "
        "{%0,%1,%2,%3}, {%4,%5,%6,%7}, {%8,%9}, {%0,%1,%2,%3};"
        : "+f"(d0), "+f"(d1), "+f"(d2), "+f"(d3)
        : "r"(a0), "r"(a1), "r"(a2), "r"(a3), "r"(b0), "r"(b1));
}

__device__ __forceinline__ uint32_t pack_bf16(float a, float b) {
    __nv_bfloat162 t(__float2bfloat16(a), __float2bfloat16(b));
    return *(uint32_t*)&t;
}

// ============ split conversion: fp32 -> (hi bf16, lo bf16) ===================
__global__ void split_kernel(const float4* __restrict__ in,
                             __nv_bfloat16* __restrict__ hi,
                             __nv_bfloat16* __restrict__ lo)
{
    int i = blockIdx.x * blockDim.x + threadIdx.x;
    float4 v = in[i];
    __nv_bfloat16 h[4], l[4];
    h[0] = __float2bfloat16(v.x); l[0] = __float2bfloat16(v.x - __bfloat162float(h[0]));
    h[1] = __float2bfloat16(v.y); l[1] = __float2bfloat16(v.y - __bfloat162float(h[1]));
    h[2] = __float2bfloat16(v.z); l[2] = __float2bfloat16(v.z - __bfloat162float(h[2]));
    h[3] = __float2bfloat16(v.w); l[3] = __float2bfloat16(v.w - __bfloat162float(h[3]));
    *(uint2*)&hi[(size_t)i * 4] = *(uint2*)h;
    *(uint2*)&lo[(size_t)i * 4] = *(uint2*)l;
}

// ===== weight transpose + split: W[K,N] fp32 -> Wt_hi/lo [N,K] bf16 ==========
__global__ void wsplit_t_kernel(const float* __restrict__ W,
                                __nv_bfloat16* __restrict__ Th,
                                __nv_bfloat16* __restrict__ Tl,
                                int K, int N)
{
    __shared__ float tile[32][33];
    int n0 = blockIdx.x * 32, k0 = blockIdx.y * 32;
    int tx = threadIdx.x, ty = threadIdx.y;   // 32 x 8
#pragma unroll
    for (int i = 0; i < 4; i++)
        tile[ty + 8 * i][tx] = W[(size_t)(k0 + ty + 8 * i) * N + n0 + tx];
    __syncthreads();
#pragma unroll
    for (int i = 0; i < 4; i++) {
        float v = tile[tx][ty + 8 * i];
        __nv_bfloat16 h = __float2bfloat16(v);
        __nv_bfloat16 l = __float2bfloat16(v - __bfloat162float(h));
        size_t o = (size_t)(n0 + ty + 8 * i) * K + k0 + tx;
        Th[o] = h;
        Tl[o] = l;
    }
}

// ====== mma.sync GEMM: C[M,N] = A[M,K] @ W[K,N], 3-term bf16 split ===========
// cp.async 2-stage pipeline, BK=32 (R9 config: 80KB smem -> 2 CTAs/SM).
#define ROWB 80
#define TILE_SB (128 * ROWB)
#define STAGE_SB (4 * TILE_SB)

__global__ void __launch_bounds__(256) gemm_mma_kernel(
    const __nv_bfloat16* __restrict__ Ah, const __nv_bfloat16* __restrict__ Al,
    const __nv_bfloat16* __restrict__ Bh, const __nv_bfloat16* __restrict__ Bl,
    float* __restrict__ C, int M, int N, int K)
{
    extern __shared__ char dsm[];
    const int tid = threadIdx.x;
    const int wid = tid >> 5, lane = tid & 31;
    const int wm = wid >> 2, wn = wid & 3;
    const int mT = blockIdx.y, nT = blockIdx.x;

    const uint32_t sbase = cvta_smem(dsm);

    const int gr  = tid >> 1;
    const int gk  = (tid & 1) * 2;
    const __nv_bfloat16* srcs[4] = {
        Ah + (size_t)(mT * 128 + gr) * K + gk * 8,
        Al + (size_t)(mT * 128 + gr) * K + gk * 8,
        Bh + (size_t)(nT * 128 + gr) * K + gk * 8,
        Bl + (size_t)(nT * 128 + gr) * K + gk * 8
    };
    const uint32_t sdst = gr * ROWB + gk * 16;

    float acc[4][4][4];
#pragma unroll
    for (int i = 0; i < 4; i++)
#pragma unroll
        for (int j = 0; j < 4; j++)
#pragma unroll
            for (int v = 0; v < 4; v++) acc[i][j][v] = 0.f;

    const int l8 = lane & 7, mi = lane >> 3;
    const uint32_t a_off = (uint32_t)(wm * 64 + l8 + ((mi & 1) << 3)) * ROWB
                         + ((mi >> 1) << 3) * 2;
    const uint32_t b_off = (uint32_t)(wn * 32 + l8 + ((mi & 1) << 3)) * ROWB
                         + ((mi >> 1) << 3) * 2;

    const int nch = K >> 5;

    // prologue: async-load stage 0
#pragma unroll
    for (int t = 0; t < 4; t++) {
        uint32_t a = sbase + t * TILE_SB + sdst;
        cp16(a, srcs[t]);
        cp16(a + 16, srcs[t] + 8);
    }
    CP_COMMIT();

    for (int ch = 0; ch < nch; ch++) {
        const uint32_t stage = sbase + (ch & 1) * STAGE_SB;
        const bool more = (ch + 1 < nch);

        if (more) {
            const int k0 = (ch + 1) << 5;
            const uint32_t nstage = sbase + ((ch + 1) & 1) * STAGE_SB;
#pragma unroll
            for (int t = 0; t < 4; t++) {
                uint32_t a = nstage + t * TILE_SB + sdst;
                cp16(a, srcs[t] + k0);
                cp16(a + 16, srcs[t] + k0 + 8);
            }
            CP_COMMIT();
            CP_WAIT(1);           // stage ch is complete
        } else {
            CP_WAIT(0);
        }
        __syncthreads();

#pragma unroll
        for (int k16 = 0; k16 < 2; k16++) {
            const uint32_t kb = k16 * 32;
            uint32_t ah[4][4], al[4][4];
#pragma unroll
            for (int i = 0; i < 4; i++) {
                uint32_t addr = stage + a_off + (uint32_t)(i * 16) * ROWB + kb;
                ldsm_x4(ah[i][0], ah[i][1], ah[i][2], ah[i][3], addr);
                ldsm_x4(al[i][0], al[i][1], al[i][2], al[i][3], addr + TILE_SB);
            }
            uint32_t bh[4][2], bl[4][2];
#pragma unroll
            for (int p = 0; p < 2; p++) {
                uint32_t addr = stage + 2 * TILE_SB + b_off + (uint32_t)(p * 16) * ROWB + kb;
                uint32_t r0, r1, r2, r3;
                ldsm_x4(r0, r1, r2, r3, addr);
                bh[2 * p][0] = r0; bh[2 * p][1] = r2;
                bh[2 * p + 1][0] = r1; bh[2 * p + 1][1] = r3;
                ldsm_x4(r0, r1, r2, r3, addr + TILE_SB);
                bl[2 * p][0] = r0; bl[2 * p][1] = r2;
                bl[2 * p + 1][0] = r1; bl[2 * p + 1][1] = r3;
            }
#pragma unroll
            for (int i = 0; i < 4; i++)
#pragma unroll
                for (int j = 0; j < 4; j++) {
                    float* d = acc[i][j];
                    mma_bf16(d[0], d[1], d[2], d[3],
                             ah[i][0], ah[i][1], ah[i][2], ah[i][3],
                             bh[j][0], bh[j][1]);
                    mma_bf16(d[0], d[1], d[2], d[3],
                             ah[i][0], ah[i][1], ah[i][2], ah[i][3],
                             bl[j][0], bl[j][1]);
                    mma_bf16(d[0], d[1], d[2], d[3],
                             al[i][0], al[i][1], al[i][2], al[i][3],
                             bh[j][0], bh[j][1]);
                }
        }
        __syncthreads();   // all warps done reading before buffer is overwritten
    }

    const int er = lane >> 2, ec = (lane & 3) * 2;
    float* Cb = C + (size_t)(mT * 128 + wm * 64 + er) * N + nT * 128 + wn * 32 + ec;
#pragma unroll
    for (int i = 0; i < 4; i++)
#pragma unroll
        for (int j = 0; j < 4; j++) {
            float* p0 = Cb + (size_t)(i * 16) * N + j * 8;
            *(float2*)p0                      = make_float2(acc[i][j][0], acc[i][j][1]);
            *(float2*)(p0 + (size_t)8 * N)    = make_float2(acc[i][j][2], acc[i][j][3]);
        }
}

// -------- RoPE q: qkv (B,S,3072) fp32 -> (B,H,S,D) bf16 hi/lo ---------------
__global__ void rope_q_kernel(const float* __restrict__ qkv,
                              __nv_bfloat16* __restrict__ qh,
                              __nv_bfloat16* __restrict__ ql,
                              const float* __restrict__ cosT, const float* __restrict__ sinT)
{
    int idx = blockIdx.x * blockDim.x + threadIdx.x;
    int d = idx & 31;
    int h = (idx >> 5) & 31;
    int s = (idx >> 10) & 2047;
    int b = idx >> 21;
    float cv = cosT[s * HD + d];
    float sv = sinT[s * HD + d];
    size_t i0 = (size_t)(b * SEQ + s) * QKVN + h * HD + d;
    float x1 = qkv[i0], x2 = qkv[i0 + 32];
    float v1 = x1 * cv - x2 * sv;
    float v2 = x2 * cv + x1 * sv;
    size_t o0 = ((size_t)(b * NH + h) * SEQ + s) * HD + d;
    __nv_bfloat16 h1 = __float2bfloat16(v1);
    __nv_bfloat16 h2 = __float2bfloat16(v2);
    qh[o0]      = h1;
    qh[o0 + 32] = h2;
    ql[o0]      = __float2bfloat16(v1 - __bfloat162float(h1));
    ql[o0 + 32] = __float2bfloat16(v2 - __bfloat162float(h2));
}

// ---- RoPE k: qkv (B,S,3072) -> fp32 next_k + bf16 hi/lo (B,KV,S,D) ---------
__global__ void rope_k_kernel(const float* __restrict__ qkv, float* __restrict__ kout,
                              __nv_bfloat16* __restrict__ kh,
                              __nv_bfloat16* __restrict__ kl,
                              const float* __restrict__ cosT, const float* __restrict__ sinT)
{
    int idx = blockIdx.x * blockDim.x + threadIdx.x;
    int d = idx & 31;
    int h = (idx >> 5) & 7;
    int s = (idx >> 8) & 2047;
    int b = idx >> 19;
    float cv = cosT[s * HD + d];
    float sv = sinT[s * HD + d];
    size_t i0 = (size_t)(b * SEQ + s) * QKVN + EMB + h * HD + d;
    float x1 = qkv[i0], x2 = qkv[i0 + 32];
    float v1 = x1 * cv - x2 * sv;
    float v2 = x2 * cv + x1 * sv;
    size_t o0 = ((size_t)(b * NKV + h) * SEQ + s) * HD + d;
    kout[o0]      = v1;
    kout[o0 + 32] = v2;
    __nv_bfloat16 h1 = __float2bfloat16(v1);
    __nv_bfloat16 h2 = __float2bfloat16(v2);
    kh[o0]      = h1;
    kh[o0 + 32] = h2;
    kl[o0]      = __float2bfloat16(v1 - __bfloat162float(h1));
    kl[o0 + 32] = __float2bfloat16(v2 - __bfloat162float(h2));
}

// -- V transpose: qkv (B,S,3072) -> fp32 next_v + bf16 hi/lo (B,KV,S,D) ------
__global__ void vtrans_kernel(const float4* __restrict__ qkv4, float4* __restrict__ vout,
                              __nv_bfloat16* __restrict__ vh,
                              __nv_bfloat16* __restrict__ vl)
{
    int idx = blockIdx.x * blockDim.x + threadIdx.x;
    int f = idx & 15;
    int h = (idx >> 4) & 7;
    int s = (idx >> 7) & 2047;
    int b = idx >> 18;
    float4 v = qkv4[(size_t)(b * SEQ + s) * (QKVN / 4) + (EMB + KVD) / 4 + h * 16 + f];
    size_t o = ((size_t)(b * NKV + h) * SEQ + s) * (HD / 4) + f;
    vout[o] = v;
    __nv_bfloat16 hh[4], ll[4];
    hh[0] = __float2bfloat16(v.x); ll[0] = __float2bfloat16(v.x - __bfloat162float(hh[0]));
    hh[1] = __float2bfloat16(v.y); ll[1] = __float2bfloat16(v.y - __bfloat162float(hh[1]));
    hh[2] = __float2bfloat16(v.z); ll[2] = __float2bfloat16(v.z - __bfloat162float(hh[2]));
    hh[3] = __float2bfloat16(v.w); ll[3] = __float2bfloat16(v.w - __bfloat162float(hh[3]));
    *(uint2*)&vh[o * 4] = *(uint2*)hh;
    *(uint2*)&vl[o * 4] = *(uint2*)ll;
}

// ---------------- causal flash attention (mma.sync bf16 split) ---------------
// BR=128 (8 warps x 16 rows), BC=64, 256 threads.
#define FROWB  144
#define FQTILE (128 * FROWB)   // 18432 per Q matrix
#define FKTILE (64 * FROWB)    // 9216 per K/V matrix
#define FSMEM  (2 * FQTILE + 4 * FKTILE)   // 73728

__global__ void __launch_bounds__(256) flash_mma_kernel(
    const __nv_bfloat16* __restrict__ Qh, const __nv_bfloat16* __restrict__ Ql,
    const __nv_bfloat16* __restrict__ Kh, const __nv_bfloat16* __restrict__ Kl,
    const __nv_bfloat16* __restrict__ Vh, const __nv_bfloat16* __restrict__ Vl,
    __nv_bfloat16* __restrict__ Oh, __nv_bfloat16* __restrict__ Ol)
{
    extern __shared__ char fsm[];
    const uint32_t sb  = cvta_smem(fsm);
    const uint32_t sQh = sb, sQl = sb + FQTILE;
    const uint32_t sKh = sb + 2 * FQTILE;
    const uint32_t sKl = sKh + FKTILE;
    const uint32_t sVh = sKh + 2 * FKTILE;
    const uint32_t sVl = sKh + 3 * FKTILE;

    const int qt = blockIdx.x, hh = blockIdx.y;
    const int b = hh >> 5, h = hh & 31, kvh = h >> 2;
    const int tid = threadIdx.x, wid = tid >> 5, lane = tid & 31;

    const __nv_bfloat16* Qhb = Qh + ((size_t)((b * NH + h) * SEQ) + qt * 128) * HD;
    const __nv_bfloat16* Qlb = Ql + ((size_t)((b * NH + h) * SEQ) + qt * 128) * HD;
    const __nv_bfloat16* Khb = Kh + (size_t)((b * NKV + kvh) * SEQ) * HD;
    const __nv_bfloat16* Klb = Kl + (size_t)((b * NKV + kvh) * SEQ) * HD;
    const __nv_bfloat16* Vhb = Vh + (size_t)((b * NKV + kvh) * SEQ) * HD;
    const __nv_bfloat16* Vlb = Vl + (size_t)((b * NKV + kvh) * SEQ) * HD;

    // load Q tiles: 256 threads, r = tid/2 (0..127), half = tid&1
    {
        const int r = tid >> 1, hf = tid & 1;
        const uint4* s0 = (const uint4*)(Qhb + (size_t)r * HD + hf * 32);
        const uint4* s1 = (const uint4*)(Qlb + (size_t)r * HD + hf * 32);
        uint32_t d0 = sQh + r * FROWB + hf * 64;
        uint32_t d1 = sQl + r * FROWB + hf * 64;
#pragma unroll
        for (int i = 0; i < 4; i++) {
            uint4 v = s0[i];
            asm volatile("st.shared.v4.b32 [%0], {%1,%2,%3,%4};"
                         :: "r"(d0 + i * 16), "r"(v.x), "r"(v.y), "r"(v.z), "r"(v.w) : "memory");
            v = s1[i];
            asm volatile("st.shared.v4.b32 [%0], {%1,%2,%3,%4};"
                         :: "r"(d1 + i * 16), "r"(v.x), "r"(v.y), "r"(v.z), "r"(v.w) : "memory");
        }
    }

    const int l8 = lane & 7, mi = lane >> 3;
    const uint32_t qa_off = (uint32_t)(wid * 16 + l8 + ((mi & 1) << 3)) * FROWB
                          + ((mi >> 1) << 4);
    const uint32_t kb_base = (uint32_t)(l8 + ((mi & 1) << 3)) * FROWB + ((mi >> 1) << 4);
    const uint32_t vb_base = (uint32_t)(((mi & 1) << 3) + l8) * FROWB + ((mi >> 1) << 4);

    float m0 = -1e30f, m1 = -1e30f, l0 = 0.f, l1 = 0.f;
    float o[8][4];
#pragma unroll
    for (int j = 0; j < 8; j++)
#pragma unroll
        for (int v = 0; v < 4; v++) o[j][v] = 0.f;

    const int rlo = wid * 16 + (lane >> 2);   // local q row (0..127)
    const int rhi = rlo + 8;

    const int ntiles = 2 * qt + 2;
    for (int kt = 0; kt < ntiles; kt++) {
        __syncthreads();
        {   // load K/V tiles: 256 threads, r = tid/4 (0..63), q4 = tid&3 (32B each)
            const int r = tid >> 2, q4 = tid & 3;
            const size_t goff = (size_t)(kt * 64 + r) * HD + q4 * 16;
            const uint32_t dof = r * FROWB + q4 * 32;
            const __nv_bfloat16* gs[4] = { Khb + goff, Klb + goff, Vhb + goff, Vlb + goff };
            const uint32_t ds[4] = { sKh + dof, sKl + dof, sVh + dof, sVl + dof };
#pragma unroll
            for (int t = 0; t < 4; t++) {
                uint4 v0 = *(const uint4*)(gs[t]);
                uint4 v1 = *(const uint4*)(gs[t] + 8);
                asm volatile("st.shared.v4.b32 [%0], {%1,%2,%3,%4};"
                             :: "r"(ds[t]), "r"(v0.x), "r"(v0.y), "r"(v0.z), "r"(v0.w) : "memory");
                asm volatile("st.shared.v4.b32 [%0], {%1,%2,%3,%4};"
                             :: "r"(ds[t] + 16), "r"(v1.x), "r"(v1.y), "r"(v1.z), "r"(v1.w) : "memory");
            }
        }
        __syncthreads();

        // ---- S = Q K^T (64 cols), 3-term split
        float sa[8][4];
#pragma unroll
        for (int j = 0; j < 8; j++)
#pragma unroll
            for (int v = 0; v < 4; v++) sa[j][v] = 0.f;

#pragma unroll
        for (int ks = 0; ks < 4; ks++) {
            uint32_t aqh[4], aql[4];
            ldsm_x4(aqh[0], aqh[1], aqh[2], aqh[3], sQh + qa_off + ks * 32);
            ldsm_x4(aql[0], aql[1], aql[2], aql[3], sQl + qa_off + ks * 32);
#pragma unroll
            for (int p = 0; p < 4; p++) {
                uint32_t addr = kb_base + (uint32_t)(p * 16) * FROWB + ks * 32;
                uint32_t r0, r1, r2, r3;
                uint32_t bh0[2], bh1[2], bl0[2], bl1[2];
                ldsm_x4(r0, r1, r2, r3, sKh + addr);
                bh0[0] = r0; bh0[1] = r2; bh1[0] = r1; bh1[1] = r3;
                ldsm_x4(r0, r1, r2, r3, sKl + addr);
                bl0[0] = r0; bl0[1] = r2; bl1[0] = r1; bl1[1] = r3;
                float* d0 = sa[2 * p];
                float* d1 = sa[2 * p + 1];
                mma_bf16(d0[0], d0[1], d0[2], d0[3], aqh[0], aqh[1], aqh[2], aqh[3], bh0[0], bh0[1]);
                mma_bf16(d0[0], d0[1], d0[2], d0[3], aqh[0], aqh[1], aqh[2], aqh[3], bl0[0], bl0[1]);
                mma_bf16(d0[0], d0[1], d0[2], d0[3], aql[0], aql[1], aql[2], aql[3], bh0[0], bh0[1]);
                mma_bf16(d1[0], d1[1], d1[2], d1[3], aqh[0], aqh[1], aqh[2], aqh[3], bh1[0], bh1[1]);
                mma_bf16(d1[0], d1[1], d1[2], d1[3], aqh[0], aqh[1], aqh[2], aqh[3], bl1[0], bl1[1]);
                mma_bf16(d1[0], d1[1], d1[2], d1[3], aql[0], aql[1], aql[2], aql[3], bh1[0], bh1[1]);
            }
        }

        // ---- scale + causal mask + online softmax (diag spans kt = 2qt, 2qt+1)
        const int ktd = kt - 2 * qt;        // >= 0 on diagonal tiles
        float mx0 = -1e30f, mx1 = -1e30f;
#pragma unroll
        for (int j = 0; j < 8; j++) {
            const int c0 = 8 * j + (lane & 3) * 2;
#pragma unroll
            for (int v = 0; v < 4; v++) {
                float sc = sa[j][v] * 0.125f;
                if (ktd >= 0) {
                    int col = c0 + (v & 1) + (ktd << 6);
                    int row = (v < 2) ? rlo : rhi;
                    if (col > row) sc = -1e30f;
                }
                sa[j][v] = sc;
            }
            mx0 = fmaxf(mx0, fmaxf(sa[j][0], sa[j][1]));
            mx1 = fmaxf(mx1, fmaxf(sa[j][2], sa[j][3]));
        }
        mx0 = fmaxf(mx0, __shfl_xor_sync(0xffffffffu, mx0, 1));
        mx0 = fmaxf(mx0, __shfl_xor_sync(0xffffffffu, mx0, 2));
        mx1 = fmaxf(mx1, __shfl_xor_sync(0xffffffffu, mx1, 1));
        mx1 = fmaxf(mx1, __shfl_xor_sync(0xffffffffu, mx1, 2));

        const float mn0 = fmaxf(m0, mx0), mn1 = fmaxf(m1, mx1);
        const float al0 = __expf(m0 - mn0), al1 = __expf(m1 - mn1);
        m0 = mn0; m1 = mn1;

        float sum0 = 0.f, sum1 = 0.f;
#pragma unroll
        for (int j = 0; j < 8; j++) {
            float e0 = __expf(sa[j][0] - mn0);
            float e1 = __expf(sa[j][1] - mn0);
            float e2 = __expf(sa[j][2] - mn1);
            float e3 = __expf(sa[j][3] - mn1);
            sa[j][0] = e0; sa[j][1] = e1; sa[j][2] = e2; sa[j][3] = e3;
            sum0 += e0 + e1;
            sum1 += e2 + e3;
        }
        sum0 += __shfl_xor_sync(0xffffffffu, sum0, 1);
        sum0 += __shfl_xor_sync(0xffffffffu, sum0, 2);
        sum1 += __shfl_xor_sync(0xffffffffu, sum1, 1);
        sum1 += __shfl_xor_sync(0xffffffffu, sum1, 2);
        l0 = l0 * al0 + sum0;
        l1 = l1 * al1 + sum1;

#pragma unroll
        for (int j = 0; j < 8; j++) {
            o[j][0] *= al0; o[j][1] *= al0;
            o[j][2] *= al1; o[j][3] *= al1;
        }

        // ---- O += P V, 3-term split (P hi/lo built in regs)
#pragma unroll
        for (int kc = 0; kc < 4; kc++) {
            const float* e0 = sa[2 * kc];
            const float* e1 = sa[2 * kc + 1];
            uint32_t ph[4], pl[4];
            ph[0] = pack_bf16(e0[0], e0[1]);
            ph[1] = pack_bf16(e0[2], e0[3]);
            ph[2] = pack_bf16(e1[0], e1[1]);
            ph[3] = pack_bf16(e1[2], e1[3]);
            {
                __nv_bfloat162 t;
                t = *(__nv_bfloat162*)&ph[0];
                pl[0] = pack_bf16(e0[0] - __bfloat162float(t.x), e0[1] - __bfloat162float(t.y));
                t = *(__nv_bfloat162*)&ph[1];
                pl[1] = pack_bf16(e0[2] - __bfloat162float(t.x), e0[3] - __bfloat162float(t.y));
                t = *(__nv_bfloat162*)&ph[2];
                pl[2] = pack_bf16(e1[0] - __bfloat162float(t.x), e1[1] - __bfloat162float(t.y));
                t = *(__nv_bfloat162*)&ph[3];
                pl[3] = pack_bf16(e1[2] - __bfloat162float(t.x), e1[3] - __bfloat162float(t.y));
            }
#pragma unroll
            for (int t4 = 0; t4 < 4; t4++) {
                uint32_t addr = vb_base + (uint32_t)(kc * 16) * FROWB + t4 * 32;
                uint32_t r0, r1, r2, r3;
                uint32_t bh0[2], bh1[2], bl0[2], bl1[2];
                ldsm_x4_t(r0, r1, r2, r3, sVh + addr);
                bh0[0] = r0; bh0[1] = r1; bh1[0] = r2; bh1[1] = r3;
                ldsm_x4_t(r0, r1, r2, r3, sVl + addr);
                bl0[0] = r0; bl0[1] = r1; bl1[0] = r2; bl1[1] = r3;
                float* d0 = o[2 * t4];
                float* d1 = o[2 * t4 + 1];
                mma_bf16(d0[0], d0[1], d0[2], d0[3], ph[0], ph[1], ph[2], ph[3], bh0[0], bh0[1]);
                mma_bf16(d0[0], d0[1], d0[2], d0[3], pl[0], pl[1], pl[2], pl[3], bh0[0], bh0[1]);
                mma_bf16(d0[0], d0[1], d0[2], d0[3], ph[0], ph[1], ph[2], ph[3], bl0[0], bl0[1]);
                mma_bf16(d1[0], d1[1], d1[2], d1[3], ph[0], ph[1], ph[2], ph[3], bh1[0], bh1[1]);
                mma_bf16(d1[0], d1[1], d1[2], d1[3], pl[0], pl[1], pl[2], pl[3], bh1[0], bh1[1]);
                mma_bf16(d1[0], d1[1], d1[2], d1[3], ph[0], ph[1], ph[2], ph[3], bl1[0], bl1[1]);
            }
        }
    }

    // ---- normalize + write hi/lo bf16 to (B,S,H,D)
    const float inv0 = 1.f / l0, inv1 = 1.f / l1;
    const int glo = qt * 128 + rlo;
    const int ghi = glo + 8;
#pragma unroll
    for (int j = 0; j < 8; j++) {
        const int d = 8 * j + (lane & 3) * 2;
        size_t plo = ((size_t)(b * SEQ + glo) * NH + h) * HD + d;
        size_t phi = ((size_t)(b * SEQ + ghi) * NH + h) * HD + d;
        float v0 = o[j][0] * inv0, v1 = o[j][1] * inv0;
        float v2 = o[j][2] * inv1, v3 = o[j][3] * inv1;
        uint32_t h01 = pack_bf16(v0, v1);
        uint32_t h23 = pack_bf16(v2, v3);
        __nv_bfloat162 th;
        th = *(__nv_bfloat162*)&h01;
        uint32_t l01 = pack_bf16(v0 - __bfloat162float(th.x), v1 - __bfloat162float(th.y));
        th = *(__nv_bfloat162*)&h23;
        uint32_t l23 = pack_bf16(v2 - __bfloat162float(th.x), v3 - __bfloat162float(th.y));
        *(uint32_t*)&Oh[plo] = h01;
        *(uint32_t*)&Ol[plo] = l01;
        *(uint32_t*)&Oh[phi] = h23;
        *(uint32_t*)&Ol[phi] = l23;
    }
}

// ---------------- launch -----------------------------------------------------
extern "C" void kernel_launch(void* const* d_in, const int* in_sizes, int n_in,
                              void* d_out, int out_size)
{
    const float* x    = (const float*)d_in[0];
    const float* cosT = (const float*)d_in[2];
    const float* sinT = (const float*)d_in[3];
    const float* Wq   = (const float*)d_in[4];
    const float* Wk   = (const float*)d_in[5];
    const float* Wv   = (const float*)d_in[6];
    const float* Wo   = (const float*)d_in[7];

    float* out = (float*)d_out;                         // (B,S,E)
    float* nk  = out + (size_t)BSZ * SEQ * EMB;         // (B,KV,S,D)
    float* nv  = nk + (size_t)BSZ * NKV * SEQ * HD;     // (B,KV,S,D)

    float* qkv_lin;
    cudaGetSymbolAddress((void**)&qkv_lin, g_qkv_lin);

    __nv_bfloat16 *xh, *xl, *ah, *al, *qh, *ql, *kh, *kl, *vh, *vl;
    __nv_bfloat16 *wqkvh, *wqkvl, *woh, *wol;
    cudaGetSymbolAddress((void**)&xh,  g_x_hi);
    cudaGetSymbolAddress((void**)&xl,  g_x_lo);
    cudaGetSymbolAddress((void**)&ah,  g_a_hi);
    cudaGetSymbolAddress((void**)&al,  g_a_lo);
    cudaGetSymbolAddress((void**)&qh,  g_qh);
    cudaGetSymbolAddress((void**)&ql,  g_ql);
    cudaGetSymbolAddress((void**)&kh,  g_kh);
    cudaGetSymbolAddress((void**)&kl,  g_kl);
    cudaGetSymbolAddress((void**)&vh,  g_vh);
    cudaGetSymbolAddress((void**)&vl,  g_vl);
    cudaGetSymbolAddress((void**)&wqkvh, g_wqkv_h);
    cudaGetSymbolAddress((void**)&wqkvl, g_wqkv_l);
    cudaGetSymbolAddress((void**)&woh, g_wo_h);
    cudaGetSymbolAddress((void**)&wol, g_wo_l);

    cudaFuncSetAttribute(gemm_mma_kernel,
                         cudaFuncAttributeMaxDynamicSharedMemorySize, 2 * STAGE_SB);
    cudaFuncSetAttribute(flash_mma_kernel,
                         cudaFuncAttributeMaxDynamicSharedMemorySize, FSMEM);

    const int M = BSZ * SEQ;          // 4096
    const size_t NX = (size_t)M * EMB;

    // split x + weights (transpose+split; QKV packed row-wise [3072 x 2048])
    split_kernel<<<(int)(NX / 4 / 256), 256>>>((const float4*)x, xh, xl);
    wsplit_t_kernel<<<dim3(EMB / 32, EMB / 32), dim3(32, 8)>>>(Wq, wqkvh, wqkvl, EMB, EMB);
    wsplit_t_kernel<<<dim3(KVD / 32, EMB / 32), dim3(32, 8)>>>(
        Wk, wqkvh + (size_t)EMB * EMB, wqkvl + (size_t)EMB * EMB, EMB, KVD);
    wsplit_t_kernel<<<dim3(KVD / 32, EMB / 32), dim3(32, 8)>>>(
        Wv, wqkvh + (size_t)(EMB + KVD) * EMB, wqkvl + (size_t)(EMB + KVD) * EMB, EMB, KVD);
    wsplit_t_kernel<<<dim3(EMB / 32, EMB / 32), dim3(32, 8)>>>(Wo, woh, wol, EMB, EMB);

    // fused QKV projection on tensor cores
    gemm_mma_kernel<<<dim3(QKVN / 128, M / 128), 256, 2 * STAGE_SB>>>(
        xh, xl, wqkvh, wqkvl, qkv_lin, M, QKVN, EMB);

    // rope + layout transforms (fp32 k/v land in d_out; bf16 splits for attn)
    rope_q_kernel<<<(BSZ * SEQ * NH * 32) / 256, 256>>>(qkv_lin, qh, ql, cosT, sinT);
    rope_k_kernel<<<(BSZ * SEQ * NKV * 32) / 256, 256>>>(qkv_lin, nk, kh, kl, cosT, sinT);
    vtrans_kernel<<<(BSZ * SEQ * NKV * 16) / 256, 256>>>(
        (const float4*)qkv_lin, (float4*)nv, vh, vl);

    // attention on tensor cores (BR=128, writes hi/lo split directly)
    flash_mma_kernel<<<dim3(SEQ / 128, BSZ * NH), 256, FSMEM>>>(
        qh, ql, kh, kl, vh, vl, ah, al);

    // output projection on tensor cores
    gemm_mma_kernel<<<dim3(EMB / 128, M / 128), 256, 2 * STAGE_SB>>>(
        ah, al, woh, wol, out, M, EMB, EMB);
}

// round 12
// speedup vs baseline: 1.1866x; 1.0104x over previous
#include <cuda_runtime.h>
#include <cuda_bf16.h>
#include <math.h>
#include <stdint.h>

#define BSZ 2
#define SEQ 2048
#define EMB 2048
#define NH  32
#define NKV 8
#define HD  64
#define KVD (NKV * HD)   // 512
#define QKVN (EMB + 2 * KVD)   // 3072

// ---------------- scratch (static device memory; no allocs allowed) ----------
// bf16 split buffers
__device__ __nv_bfloat16 g_x_hi[BSZ * SEQ * EMB];
__device__ __nv_bfloat16 g_x_lo[BSZ * SEQ * EMB];
__device__ __nv_bfloat16 g_a_hi[BSZ * SEQ * EMB];   // attn out hi (B,S,H,D)
__device__ __nv_bfloat16 g_a_lo[BSZ * SEQ * EMB];   // attn out lo
__device__ __nv_bfloat16 g_qh[BSZ * SEQ * EMB];     // rope'd q hi (B,H,S,D)
__device__ __nv_bfloat16 g_ql[BSZ * SEQ * EMB];
__device__ __nv_bfloat16 g_kh[BSZ * SEQ * KVD];     // rope'd k hi (B,KV,S,D)
__device__ __nv_bfloat16 g_kl[BSZ * SEQ * KVD];
__device__ __nv_bfloat16 g_vh[BSZ * SEQ * KVD];     // v hi (B,KV,S,D)
__device__ __nv_bfloat16 g_vl[BSZ * SEQ * KVD];
__device__ __nv_bfloat16 g_wqkv_h[QKVN * EMB];      // packed [Wq;Wk;Wv]^T hi
__device__ __nv_bfloat16 g_wqkv_l[QKVN * EMB];
__device__ __nv_bfloat16 g_wo_h[EMB * EMB];
__device__ __nv_bfloat16 g_wo_l[EMB * EMB];

// ======================= helpers =============================================
__device__ __forceinline__ uint32_t cvta_smem(const void* p) {
    uint32_t a;
    asm("{ .reg .u64 t; cvta.to.shared.u64 t, %1; cvt.u32.u64 %0, t; }"
        : "=r"(a) : "l"(p));
    return a;
}

__device__ __forceinline__ void cp16(uint32_t dst, const void* src) {
    asm volatile("cp.async.cg.shared.global [%0], [%1], 16;"
                 :: "r"(dst), "l"(src) : "memory");
}
#define CP_COMMIT() asm volatile("cp.async.commit_group;" ::: "memory")
#define CP_WAIT(n)  asm volatile("cp.async.wait_group %0;" :: "n"(n) : "memory")

__device__ __forceinline__ void ldsm_x4(uint32_t& r0, uint32_t& r1,
                                        uint32_t& r2, uint32_t& r3, uint32_t addr) {
    asm volatile("ldmatrix.sync.aligned.m8n8.x4.shared.b16 {%0,%1,%2,%3}, [%4];"
                 : "=r"(r0), "=r"(r1), "=r"(r2), "=r"(r3) : "r"(addr));
}

__device__ __forceinline__ void ldsm_x4_t(uint32_t& r0, uint32_t& r1,
                                          uint32_t& r2, uint32_t& r3, uint32_t addr) {
    asm volatile("ldmatrix.sync.aligned.m8n8.x4.trans.shared.b16 {%0,%1,%2,%3}, [%4];"
                 : "=r"(r0), "=r"(r1), "=r"(r2), "=r"(r3) : "r"(addr));
}

__device__ __forceinline__ void mma_bf16(float& d0, float& d1, float& d2, float& d3,
                                         uint32_t a0, uint32_t a1, uint32_t a2, uint32_t a3,
                                         uint32_t b0, uint32_t b1) {
    asm volatile(
        "mma.sync.aligned.m16n8k16.row.col.f32.bf16.bf16.f32 "
        "{%0,%1,%2,%3}, {%4,%5,%6,%7}, {%8,%9}, {%0,%1,%2,%3};"
        : "+f"(d0), "+f"(d1), "+f"(d2), "+f"(d3)
        : "r"(a0), "r"(a1), "r"(a2), "r"(a3), "r"(b0), "r"(b1));
}

__device__ __forceinline__ uint32_t pack_bf16(float a, float b) {
    __nv_bfloat162 t(__float2bfloat16(a), __float2bfloat16(b));
    return *(uint32_t*)&t;
}

// ============ split conversion: fp32 -> (hi bf16, lo bf16) ===================
__global__ void split_kernel(const float4* __restrict__ in,
                             __nv_bfloat16* __restrict__ hi,
                             __nv_bfloat16* __restrict__ lo)
{
    int i = blockIdx.x * blockDim.x + threadIdx.x;
    float4 v = in[i];
    __nv_bfloat16 h[4], l[4];
    h[0] = __float2bfloat16(v.x); l[0] = __float2bfloat16(v.x - __bfloat162float(h[0]));
    h[1] = __float2bfloat16(v.y); l[1] = __float2bfloat16(v.y - __bfloat162float(h[1]));
    h[2] = __float2bfloat16(v.z); l[2] = __float2bfloat16(v.z - __bfloat162float(h[2]));
    h[3] = __float2bfloat16(v.w); l[3] = __float2bfloat16(v.w - __bfloat162float(h[3]));
    *(uint2*)&hi[(size_t)i * 4] = *(uint2*)h;
    *(uint2*)&lo[(size_t)i * 4] = *(uint2*)l;
}

// ===== weight transpose + split: W[K,N] fp32 -> Wt_hi/lo [N,K] bf16 ==========
__global__ void wsplit_t_kernel(const float* __restrict__ W,
                                __nv_bfloat16* __restrict__ Th,
                                __nv_bfloat16* __restrict__ Tl,
                                int K, int N)
{
    __shared__ float tile[32][33];
    int n0 = blockIdx.x * 32, k0 = blockIdx.y * 32;
    int tx = threadIdx.x, ty = threadIdx.y;   // 32 x 8
#pragma unroll
    for (int i = 0; i < 4; i++)
        tile[ty + 8 * i][tx] = W[(size_t)(k0 + ty + 8 * i) * N + n0 + tx];
    __syncthreads();
#pragma unroll
    for (int i = 0; i < 4; i++) {
        float v = tile[tx][ty + 8 * i];
        __nv_bfloat16 h = __float2bfloat16(v);
        __nv_bfloat16 l = __float2bfloat16(v - __bfloat162float(h));
        size_t o = (size_t)(n0 + ty + 8 * i) * K + k0 + tx;
        Th[o] = h;
        Tl[o] = l;
    }
}

// ====== shared GEMM mainloop config (BK=32, 80KB smem -> 2 CTAs/SM) ==========
#define ROWB 80
#define TILE_SB (128 * ROWB)
#define STAGE_SB (4 * TILE_SB)

// Mainloop as a macro-free inline: computes acc[4][4][4] for tile (mT,nT).
// (duplicated in two kernels; shared via this helper)
__device__ __forceinline__ void gemm_mainloop(
    const __nv_bfloat16* __restrict__ Ah, const __nv_bfloat16* __restrict__ Al,
    const __nv_bfloat16* __restrict__ Bh, const __nv_bfloat16* __restrict__ Bl,
    int K, int mT, int nT, char* dsm, float acc[4][4][4])
{
    const int tid = threadIdx.x;
    const int wid = tid >> 5, lane = tid & 31;
    const int wm = wid >> 2, wn = wid & 3;
    const uint32_t sbase = cvta_smem(dsm);

    const int gr  = tid >> 1;
    const int gk  = (tid & 1) * 2;
    const __nv_bfloat16* srcs[4] = {
        Ah + (size_t)(mT * 128 + gr) * K + gk * 8,
        Al + (size_t)(mT * 128 + gr) * K + gk * 8,
        Bh + (size_t)(nT * 128 + gr) * K + gk * 8,
        Bl + (size_t)(nT * 128 + gr) * K + gk * 8
    };
    const uint32_t sdst = gr * ROWB + gk * 16;

#pragma unroll
    for (int i = 0; i < 4; i++)
#pragma unroll
        for (int j = 0; j < 4; j++)
#pragma unroll
            for (int v = 0; v < 4; v++) acc[i][j][v] = 0.f;

    const int l8 = lane & 7, mi = lane >> 3;
    const uint32_t a_off = (uint32_t)(wm * 64 + l8 + ((mi & 1) << 3)) * ROWB
                         + ((mi >> 1) << 3) * 2;
    const uint32_t b_off = (uint32_t)(wn * 32 + l8 + ((mi & 1) << 3)) * ROWB
                         + ((mi >> 1) << 3) * 2;

    const int nch = K >> 5;

#pragma unroll
    for (int t = 0; t < 4; t++) {
        uint32_t a = sbase + t * TILE_SB + sdst;
        cp16(a, srcs[t]);
        cp16(a + 16, srcs[t] + 8);
    }
    CP_COMMIT();

    for (int ch = 0; ch < nch; ch++) {
        const uint32_t stage = sbase + (ch & 1) * STAGE_SB;
        const bool more = (ch + 1 < nch);

        if (more) {
            const int k0 = (ch + 1) << 5;
            const uint32_t nstage = sbase + ((ch + 1) & 1) * STAGE_SB;
#pragma unroll
            for (int t = 0; t < 4; t++) {
                uint32_t a = nstage + t * TILE_SB + sdst;
                cp16(a, srcs[t] + k0);
                cp16(a + 16, srcs[t] + k0 + 8);
            }
            CP_COMMIT();
            CP_WAIT(1);
        } else {
            CP_WAIT(0);
        }
        __syncthreads();

#pragma unroll
        for (int k16 = 0; k16 < 2; k16++) {
            const uint32_t kb = k16 * 32;
            uint32_t ah[4][4], al[4][4];
#pragma unroll
            for (int i = 0; i < 4; i++) {
                uint32_t addr = stage + a_off + (uint32_t)(i * 16) * ROWB + kb;
                ldsm_x4(ah[i][0], ah[i][1], ah[i][2], ah[i][3], addr);
                ldsm_x4(al[i][0], al[i][1], al[i][2], al[i][3], addr + TILE_SB);
            }
            uint32_t bh[4][2], bl[4][2];
#pragma unroll
            for (int p = 0; p < 2; p++) {
                uint32_t addr = stage + 2 * TILE_SB + b_off + (uint32_t)(p * 16) * ROWB + kb;
                uint32_t r0, r1, r2, r3;
                ldsm_x4(r0, r1, r2, r3, addr);
                bh[2 * p][0] = r0; bh[2 * p][1] = r2;
                bh[2 * p + 1][0] = r1; bh[2 * p + 1][1] = r3;
                ldsm_x4(r0, r1, r2, r3, addr + TILE_SB);
                bl[2 * p][0] = r0; bl[2 * p][1] = r2;
                bl[2 * p + 1][0] = r1; bl[2 * p + 1][1] = r3;
            }
#pragma unroll
            for (int i = 0; i < 4; i++)
#pragma unroll
                for (int j = 0; j < 4; j++) {
                    float* d = acc[i][j];
                    mma_bf16(d[0], d[1], d[2], d[3],
                             ah[i][0], ah[i][1], ah[i][2], ah[i][3],
                             bh[j][0], bh[j][1]);
                    mma_bf16(d[0], d[1], d[2], d[3],
                             ah[i][0], ah[i][1], ah[i][2], ah[i][3],
                             bl[j][0], bl[j][1]);
                    mma_bf16(d[0], d[1], d[2], d[3],
                             al[i][0], al[i][1], al[i][2], al[i][3],
                             bh[j][0], bh[j][1]);
                }
        }
        __syncthreads();
    }
}

// ---------------- Wo GEMM: plain fp32 C output -------------------------------
__global__ void __launch_bounds__(256) gemm_mma_kernel(
    const __nv_bfloat16* __restrict__ Ah, const __nv_bfloat16* __restrict__ Al,
    const __nv_bfloat16* __restrict__ Bh, const __nv_bfloat16* __restrict__ Bl,
    float* __restrict__ C, int M, int N, int K)
{
    extern __shared__ char dsm[];
    float acc[4][4][4];
    gemm_mainloop(Ah, Al, Bh, Bl, K, blockIdx.y, blockIdx.x, dsm, acc);

    const int tid = threadIdx.x;
    const int wid = tid >> 5, lane = tid & 31;
    const int wm = wid >> 3 ? 0 : 0;   // placeholder (recomputed below)
    (void)wm;
    const int wmm = (tid >> 5) >> 2, wnn = (tid >> 5) & 3;
    const int er = lane >> 2, ec = (lane & 3) * 2;
    float* Cb = C + (size_t)(blockIdx.y * 128 + wmm * 64 + er) * N
              + blockIdx.x * 128 + wnn * 32 + ec;
#pragma unroll
    for (int i = 0; i < 4; i++)
#pragma unroll
        for (int j = 0; j < 4; j++) {
            float* p0 = Cb + (size_t)(i * 16) * N + j * 8;
            *(float2*)p0                      = make_float2(acc[i][j][0], acc[i][j][1]);
            *(float2*)(p0 + (size_t)8 * N)    = make_float2(acc[i][j][2], acc[i][j][3]);
        }
}

// ------- QKV GEMM with fused RoPE/vtrans/split epilogue ----------------------
// nT 0..15: Q -> rope -> qh/ql (B,H,S,D)
// nT 16..19: K -> rope -> nk fp32 + kh/kl (B,KV,S,D)
// nT 20..23: V -> copy -> nv fp32 + vh/vl (B,KV,S,D)
#define CTP 132   // smem C-tile pitch (floats)

__global__ void __launch_bounds__(256) gemm_qkv_kernel(
    const __nv_bfloat16* __restrict__ Ah, const __nv_bfloat16* __restrict__ Al,
    const __nv_bfloat16* __restrict__ Bh, const __nv_bfloat16* __restrict__ Bl,
    int K,
    __nv_bfloat16* __restrict__ qh, __nv_bfloat16* __restrict__ ql,
    __nv_bfloat16* __restrict__ kh, __nv_bfloat16* __restrict__ kl,
    __nv_bfloat16* __restrict__ vh, __nv_bfloat16* __restrict__ vl,
    float* __restrict__ nk, float* __restrict__ nv,
    const float* __restrict__ cosT, const float* __restrict__ sinT)
{
    extern __shared__ char dsm[];
    const int mT = blockIdx.y, nT = blockIdx.x;
    float acc[4][4][4];
    gemm_mainloop(Ah, Al, Bh, Bl, K, mT, nT, dsm, acc);

    // park C tile in smem (pipeline stages are free after the mainloop)
    const int tid = threadIdx.x;
    const int wid = tid >> 5, lane = tid & 31;
    const int wm = wid >> 2, wn = wid & 3;
    const int er = lane >> 2, ec = (lane & 3) * 2;
    float* Ct = (float*)dsm;
#pragma unroll
    for (int i = 0; i < 4; i++) {
        const int r0 = wm * 64 + i * 16 + er;
#pragma unroll
        for (int j = 0; j < 4; j++) {
            const int c = wn * 32 + j * 8 + ec;
            Ct[r0 * CTP + c]           = acc[i][j][0];
            Ct[r0 * CTP + c + 1]       = acc[i][j][1];
            Ct[(r0 + 8) * CTP + c]     = acc[i][j][2];
            Ct[(r0 + 8) * CTP + c + 1] = acc[i][j][3];
        }
    }
    __syncthreads();

    if (nT < 20) {
        // rope path (Q or K). 8192 pairs, 32 per thread.
        const bool isQ = (nT < 16);
#pragma unroll 4
        for (int it = 0; it < 32; it++) {
            const int p  = tid + (it << 8);
            const int d  = p & 31;
            const int hd = (p >> 5) & 1;
            const int r  = p >> 6;
            const int gm = mT * 128 + r;
            const int b = gm >> 11, s = gm & 2047;
            const float cv = cosT[s * HD + d];
            const float sv = sinT[s * HD + d];
            const float x1 = Ct[r * CTP + hd * 64 + d];
            const float x2 = Ct[r * CTP + hd * 64 + d + 32];
            const float v1 = x1 * cv - x2 * sv;
            const float v2 = x2 * cv + x1 * sv;
            const __nv_bfloat16 h1 = __float2bfloat16(v1);
            const __nv_bfloat16 h2 = __float2bfloat16(v2);
            const __nv_bfloat16 l1 = __float2bfloat16(v1 - __bfloat162float(h1));
            const __nv_bfloat16 l2 = __float2bfloat16(v2 - __bfloat162float(h2));
            if (isQ) {
                const int h = nT * 2 + hd;
                const size_t o0 = ((size_t)(b * NH + h) * SEQ + s) * HD + d;
                qh[o0] = h1; qh[o0 + 32] = h2;
                ql[o0] = l1; ql[o0 + 32] = l2;
            } else {
                const int kvh = (nT - 16) * 2 + hd;
                const size_t o0 = ((size_t)(b * NKV + kvh) * SEQ + s) * HD + d;
                nk[o0] = v1; nk[o0 + 32] = v2;
                kh[o0] = h1; kh[o0 + 32] = h2;
                kl[o0] = l1; kl[o0 + 32] = l2;
            }
        }
    } else {
        // V path: plain copy + split, float4-wide.
        const int c4 = (tid & 31) * 4;    // 0..124
        const int rr = tid >> 5;          // 0..7
        const int hd = c4 >> 6;
        const int d4 = c4 & 63;
        const int kvh = (nT - 20) * 2 + hd;
#pragma unroll 4
        for (int i = 0; i < 16; i++) {
            const int r = rr + i * 8;
            const int gm = mT * 128 + r;
            const int b = gm >> 11, s = gm & 2047;
            float4 v = *(float4*)&Ct[r * CTP + c4];
            const size_t o = ((size_t)(b * NKV + kvh) * SEQ + s) * HD + d4;
            *(float4*)&nv[o] = v;
            __nv_bfloat16 hh[4], ll[4];
            hh[0] = __float2bfloat16(v.x); ll[0] = __float2bfloat16(v.x - __bfloat162float(hh[0]));
            hh[1] = __float2bfloat16(v.y); ll[1] = __float2bfloat16(v.y - __bfloat162float(hh[1]));
            hh[2] = __float2bfloat16(v.z); ll[2] = __float2bfloat16(v.z - __bfloat162float(hh[2]));
            hh[3] = __float2bfloat16(v.w); ll[3] = __float2bfloat16(v.w - __bfloat162float(hh[3]));
            *(uint2*)&vh[o] = *(uint2*)hh;
            *(uint2*)&vl[o] = *(uint2*)ll;
        }
    }
}

// ---------------- causal flash attention (mma.sync bf16 split) ---------------
// BR=128 (8 warps x 16 rows), BC=64, 256 threads.
#define FROWB  144
#define FQTILE (128 * FROWB)   // 18432 per Q matrix
#define FKTILE (64 * FROWB)    // 9216 per K/V matrix
#define FSMEM  (2 * FQTILE + 4 * FKTILE)   // 73728

__global__ void __launch_bounds__(256) flash_mma_kernel(
    const __nv_bfloat16* __restrict__ Qh, const __nv_bfloat16* __restrict__ Ql,
    const __nv_bfloat16* __restrict__ Kh, const __nv_bfloat16* __restrict__ Kl,
    const __nv_bfloat16* __restrict__ Vh, const __nv_bfloat16* __restrict__ Vl,
    __nv_bfloat16* __restrict__ Oh, __nv_bfloat16* __restrict__ Ol)
{
    extern __shared__ char fsm[];
    const uint32_t sb  = cvta_smem(fsm);
    const uint32_t sQh = sb, sQl = sb + FQTILE;
    const uint32_t sKh = sb + 2 * FQTILE;
    const uint32_t sKl = sKh + FKTILE;
    const uint32_t sVh = sKh + 2 * FKTILE;
    const uint32_t sVl = sKh + 3 * FKTILE;

    const int qt = blockIdx.x, hh = blockIdx.y;
    const int b = hh >> 5, h = hh & 31, kvh = h >> 2;
    const int tid = threadIdx.x, wid = tid >> 5, lane = tid & 31;

    const __nv_bfloat16* Qhb = Qh + ((size_t)((b * NH + h) * SEQ) + qt * 128) * HD;
    const __nv_bfloat16* Qlb = Ql + ((size_t)((b * NH + h) * SEQ) + qt * 128) * HD;
    const __nv_bfloat16* Khb = Kh + (size_t)((b * NKV + kvh) * SEQ) * HD;
    const __nv_bfloat16* Klb = Kl + (size_t)((b * NKV + kvh) * SEQ) * HD;
    const __nv_bfloat16* Vhb = Vh + (size_t)((b * NKV + kvh) * SEQ) * HD;
    const __nv_bfloat16* Vlb = Vl + (size_t)((b * NKV + kvh) * SEQ) * HD;

    {
        const int r = tid >> 1, hf = tid & 1;
        const uint4* s0 = (const uint4*)(Qhb + (size_t)r * HD + hf * 32);
        const uint4* s1 = (const uint4*)(Qlb + (size_t)r * HD + hf * 32);
        uint32_t d0 = sQh + r * FROWB + hf * 64;
        uint32_t d1 = sQl + r * FROWB + hf * 64;
#pragma unroll
        for (int i = 0; i < 4; i++) {
            uint4 v = s0[i];
            asm volatile("st.shared.v4.b32 [%0], {%1,%2,%3,%4};"
                         :: "r"(d0 + i * 16), "r"(v.x), "r"(v.y), "r"(v.z), "r"(v.w) : "memory");
            v = s1[i];
            asm volatile("st.shared.v4.b32 [%0], {%1,%2,%3,%4};"
                         :: "r"(d1 + i * 16), "r"(v.x), "r"(v.y), "r"(v.z), "r"(v.w) : "memory");
        }
    }

    const int l8 = lane & 7, mi = lane >> 3;
    const uint32_t qa_off = (uint32_t)(wid * 16 + l8 + ((mi & 1) << 3)) * FROWB
                          + ((mi >> 1) << 4);
    const uint32_t kb_base = (uint32_t)(l8 + ((mi & 1) << 3)) * FROWB + ((mi >> 1) << 4);
    const uint32_t vb_base = (uint32_t)(((mi & 1) << 3) + l8) * FROWB + ((mi >> 1) << 4);

    float m0 = -1e30f, m1 = -1e30f, l0 = 0.f, l1 = 0.f;
    float o[8][4];
#pragma unroll
    for (int j = 0; j < 8; j++)
#pragma unroll
        for (int v = 0; v < 4; v++) o[j][v] = 0.f;

    const int rlo = wid * 16 + (lane >> 2);
    const int rhi = rlo + 8;

    const int ntiles = 2 * qt + 2;
    for (int kt = 0; kt < ntiles; kt++) {
        __syncthreads();
        {
            const int r = tid >> 2, q4 = tid & 3;
            const size_t goff = (size_t)(kt * 64 + r) * HD + q4 * 16;
            const uint32_t dof = r * FROWB + q4 * 32;
            const __nv_bfloat16* gs[4] = { Khb + goff, Klb + goff, Vhb + goff, Vlb + goff };
            const uint32_t ds[4] = { sKh + dof, sKl + dof, sVh + dof, sVl + dof };
#pragma unroll
            for (int t = 0; t < 4; t++) {
                uint4 v0 = *(const uint4*)(gs[t]);
                uint4 v1 = *(const uint4*)(gs[t] + 8);
                asm volatile("st.shared.v4.b32 [%0], {%1,%2,%3,%4};"
                             :: "r"(ds[t]), "r"(v0.x), "r"(v0.y), "r"(v0.z), "r"(v0.w) : "memory");
                asm volatile("st.shared.v4.b32 [%0], {%1,%2,%3,%4};"
                             :: "r"(ds[t] + 16), "r"(v1.x), "r"(v1.y), "r"(v1.z), "r"(v1.w) : "memory");
            }
        }
        __syncthreads();

        float sa[8][4];
#pragma unroll
        for (int j = 0; j < 8; j++)
#pragma unroll
            for (int v = 0; v < 4; v++) sa[j][v] = 0.f;

#pragma unroll
        for (int ks = 0; ks < 4; ks++) {
            uint32_t aqh[4], aql[4];
            ldsm_x4(aqh[0], aqh[1], aqh[2], aqh[3], sQh + qa_off + ks * 32);
            ldsm_x4(aql[0], aql[1], aql[2], aql[3], sQl + qa_off + ks * 32);
#pragma unroll
            for (int p = 0; p < 4; p++) {
                uint32_t addr = kb_base + (uint32_t)(p * 16) * FROWB + ks * 32;
                uint32_t r0, r1, r2, r3;
                uint32_t bh0[2], bh1[2], bl0[2], bl1[2];
                ldsm_x4(r0, r1, r2, r3, sKh + addr);
                bh0[0] = r0; bh0[1] = r2; bh1[0] = r1; bh1[1] = r3;
                ldsm_x4(r0, r1, r2, r3, sKl + addr);
                bl0[0] = r0; bl0[1] = r2; bl1[0] = r1; bl1[1] = r3;
                float* d0 = sa[2 * p];
                float* d1 = sa[2 * p + 1];
                mma_bf16(d0[0], d0[1], d0[2], d0[3], aqh[0], aqh[1], aqh[2], aqh[3], bh0[0], bh0[1]);
                mma_bf16(d0[0], d0[1], d0[2], d0[3], aqh[0], aqh[1], aqh[2], aqh[3], bl0[0], bl0[1]);
                mma_bf16(d0[0], d0[1], d0[2], d0[3], aql[0], aql[1], aql[2], aql[3], bh0[0], bh0[1]);
                mma_bf16(d1[0], d1[1], d1[2], d1[3], aqh[0], aqh[1], aqh[2], aqh[3], bh1[0], bh1[1]);
                mma_bf16(d1[0], d1[1], d1[2], d1[3], aqh[0], aqh[1], aqh[2], aqh[3], bl1[0], bl1[1]);
                mma_bf16(d1[0], d1[1], d1[2], d1[3], aql[0], aql[1], aql[2], aql[3], bh1[0], bh1[1]);
            }
        }

        const int ktd = kt - 2 * qt;
        float mx0 = -1e30f, mx1 = -1e30f;
#pragma unroll
        for (int j = 0; j < 8; j++) {
            const int c0 = 8 * j + (lane & 3) * 2;
#pragma unroll
            for (int v = 0; v < 4; v++) {
                float sc = sa[j][v] * 0.125f;
                if (ktd >= 0) {
                    int col = c0 + (v & 1) + (ktd << 6);
                    int row = (v < 2) ? rlo : rhi;
                    if (col > row) sc = -1e30f;
                }
                sa[j][v] = sc;
            }
            mx0 = fmaxf(mx0, fmaxf(sa[j][0], sa[j][1]));
            mx1 = fmaxf(mx1, fmaxf(sa[j][2], sa[j][3]));
        }
        mx0 = fmaxf(mx0, __shfl_xor_sync(0xffffffffu, mx0, 1));
        mx0 = fmaxf(mx0, __shfl_xor_sync(0xffffffffu, mx0, 2));
        mx1 = fmaxf(mx1, __shfl_xor_sync(0xffffffffu, mx1, 1));
        mx1 = fmaxf(mx1, __shfl_xor_sync(0xffffffffu, mx1, 2));

        const float mn0 = fmaxf(m0, mx0), mn1 = fmaxf(m1, mx1);
        const float al0 = __expf(m0 - mn0), al1 = __expf(m1 - mn1);
        m0 = mn0; m1 = mn1;

        float sum0 = 0.f, sum1 = 0.f;
#pragma unroll
        for (int j = 0; j < 8; j++) {
            float e0 = __expf(sa[j][0] - mn0);
            float e1 = __expf(sa[j][1] - mn0);
            float e2 = __expf(sa[j][2] - mn1);
            float e3 = __expf(sa[j][3] - mn1);
            sa[j][0] = e0; sa[j][1] = e1; sa[j][2] = e2; sa[j][3] = e3;
            sum0 += e0 + e1;
            sum1 += e2 + e3;
        }
        sum0 += __shfl_xor_sync(0xffffffffu, sum0, 1);
        sum0 += __shfl_xor_sync(0xffffffffu, sum0, 2);
        sum1 += __shfl_xor_sync(0xffffffffu, sum1, 1);
        sum1 += __shfl_xor_sync(0xffffffffu, sum1, 2);
        l0 = l0 * al0 + sum0;
        l1 = l1 * al1 + sum1;

#pragma unroll
        for (int j = 0; j < 8; j++) {
            o[j][0] *= al0; o[j][1] *= al0;
            o[j][2] *= al1; o[j][3] *= al1;
        }

#pragma unroll
        for (int kc = 0; kc < 4; kc++) {
            const float* e0 = sa[2 * kc];
            const float* e1 = sa[2 * kc + 1];
            uint32_t ph[4], pl[4];
            ph[0] = pack_bf16(e0[0], e0[1]);
            ph[1] = pack_bf16(e0[2], e0[3]);
            ph[2] = pack_bf16(e1[0], e1[1]);
            ph[3] = pack_bf16(e1[2], e1[3]);
            {
                __nv_bfloat162 t;
                t = *(__nv_bfloat162*)&ph[0];
                pl[0] = pack_bf16(e0[0] - __bfloat162float(t.x), e0[1] - __bfloat162float(t.y));
                t = *(__nv_bfloat162*)&ph[1];
                pl[1] = pack_bf16(e0[2] - __bfloat162float(t.x), e0[3] - __bfloat162float(t.y));
                t = *(__nv_bfloat162*)&ph[2];
                pl[2] = pack_bf16(e1[0] - __bfloat162float(t.x), e1[1] - __bfloat162float(t.y));
                t = *(__nv_bfloat162*)&ph[3];
                pl[3] = pack_bf16(e1[2] - __bfloat162float(t.x), e1[3] - __bfloat162float(t.y));
            }
#pragma unroll
            for (int t4 = 0; t4 < 4; t4++) {
                uint32_t addr = vb_base + (uint32_t)(kc * 16) * FROWB + t4 * 32;
                uint32_t r0, r1, r2, r3;
                uint32_t bh0[2], bh1[2], bl0[2], bl1[2];
                ldsm_x4_t(r0, r1, r2, r3, sVh + addr);
                bh0[0] = r0; bh0[1] = r1; bh1[0] = r2; bh1[1] = r3;
                ldsm_x4_t(r0, r1, r2, r3, sVl + addr);
                bl0[0] = r0; bl0[1] = r1; bl1[0] = r2; bl1[1] = r3;
                float* d0 = o[2 * t4];
                float* d1 = o[2 * t4 + 1];
                mma_bf16(d0[0], d0[1], d0[2], d0[3], ph[0], ph[1], ph[2], ph[3], bh0[0], bh0[1]);
                mma_bf16(d0[0], d0[1], d0[2], d0[3], pl[0], pl[1], pl[2], pl[3], bh0[0], bh0[1]);
                mma_bf16(d0[0], d0[1], d0[2], d0[3], ph[0], ph[1], ph[2], ph[3], bl0[0], bl0[1]);
                mma_bf16(d1[0], d1[1], d1[2], d1[3], ph[0], ph[1], ph[2], ph[3], bh1[0], bh1[1]);
                mma_bf16(d1[0], d1[1], d1[2], d1[3], pl[0], pl[1], pl[2], pl[3], bh1[0], bh1[1]);
                mma_bf16(d1[0], d1[1], d1[2], d1[3], ph[0], ph[1], ph[2], ph[3], bl1[0], bl1[1]);
            }
        }
    }

    const float inv0 = 1.f / l0, inv1 = 1.f / l1;
    const int glo = qt * 128 + rlo;
    const int ghi = glo + 8;
#pragma unroll
    for (int j = 0; j < 8; j++) {
        const int d = 8 * j + (lane & 3) * 2;
        size_t plo = ((size_t)(b * SEQ + glo) * NH + h) * HD + d;
        size_t phi = ((size_t)(b * SEQ + ghi) * NH + h) * HD + d;
        float v0 = o[j][0] * inv0, v1 = o[j][1] * inv0;
        float v2 = o[j][2] * inv1, v3 = o[j][3] * inv1;
        uint32_t h01 = pack_bf16(v0, v1);
        uint32_t h23 = pack_bf16(v2, v3);
        __nv_bfloat162 th;
        th = *(__nv_bfloat162*)&h01;
        uint32_t l01 = pack_bf16(v0 - __bfloat162float(th.x), v1 - __bfloat162float(th.y));
        th = *(__nv_bfloat162*)&h23;
        uint32_t l23 = pack_bf16(v2 - __bfloat162float(th.x), v3 - __bfloat162float(th.y));
        *(uint32_t*)&Oh[plo] = h01;
        *(uint32_t*)&Ol[plo] = l01;
        *(uint32_t*)&Oh[phi] = h23;
        *(uint32_t*)&Ol[phi] = l23;
    }
}

// ---------------- launch -----------------------------------------------------
extern "C" void kernel_launch(void* const* d_in, const int* in_sizes, int n_in,
                              void* d_out, int out_size)
{
    const float* x    = (const float*)d_in[0];
    const float* cosT = (const float*)d_in[2];
    const float* sinT = (const float*)d_in[3];
    const float* Wq   = (const float*)d_in[4];
    const float* Wk   = (const float*)d_in[5];
    const float* Wv   = (const float*)d_in[6];
    const float* Wo   = (const float*)d_in[7];

    float* out = (float*)d_out;                         // (B,S,E)
    float* nk  = out + (size_t)BSZ * SEQ * EMB;         // (B,KV,S,D)
    float* nv  = nk + (size_t)BSZ * NKV * SEQ * HD;     // (B,KV,S,D)

    __nv_bfloat16 *xh, *xl, *ah, *al, *qh, *ql, *kh, *kl, *vh, *vl;
    __nv_bfloat16 *wqkvh, *wqkvl, *woh, *wol;
    cudaGetSymbolAddress((void**)&xh,  g_x_hi);
    cudaGetSymbolAddress((void**)&xl,  g_x_lo);
    cudaGetSymbolAddress((void**)&ah,  g_a_hi);
    cudaGetSymbolAddress((void**)&al,  g_a_lo);
    cudaGetSymbolAddress((void**)&qh,  g_qh);
    cudaGetSymbolAddress((void**)&ql,  g_ql);
    cudaGetSymbolAddress((void**)&kh,  g_kh);
    cudaGetSymbolAddress((void**)&kl,  g_kl);
    cudaGetSymbolAddress((void**)&vh,  g_vh);
    cudaGetSymbolAddress((void**)&vl,  g_vl);
    cudaGetSymbolAddress((void**)&wqkvh, g_wqkv_h);
    cudaGetSymbolAddress((void**)&wqkvl, g_wqkv_l);
    cudaGetSymbolAddress((void**)&woh, g_wo_h);
    cudaGetSymbolAddress((void**)&wol, g_wo_l);

    cudaFuncSetAttribute(gemm_mma_kernel,
                         cudaFuncAttributeMaxDynamicSharedMemorySize, 2 * STAGE_SB);
    cudaFuncSetAttribute(gemm_qkv_kernel,
                         cudaFuncAttributeMaxDynamicSharedMemorySize, 2 * STAGE_SB);
    cudaFuncSetAttribute(flash_mma_kernel,
                         cudaFuncAttributeMaxDynamicSharedMemorySize, FSMEM);

    const int M = BSZ * SEQ;          // 4096
    const size_t NX = (size_t)M * EMB;

    // split x + weights (transpose+split; QKV packed row-wise [3072 x 2048])
    split_kernel<<<(int)(NX / 4 / 256), 256>>>((const float4*)x, xh, xl);
    wsplit_t_kernel<<<dim3(EMB / 32, EMB / 32), dim3(32, 8)>>>(Wq, wqkvh, wqkvl, EMB, EMB);
    wsplit_t_kernel<<<dim3(KVD / 32, EMB / 32), dim3(32, 8)>>>(
        Wk, wqkvh + (size_t)EMB * EMB, wqkvl + (size_t)EMB * EMB, EMB, KVD);
    wsplit_t_kernel<<<dim3(KVD / 32, EMB / 32), dim3(32, 8)>>>(
        Wv, wqkvh + (size_t)(EMB + KVD) * EMB, wqkvl + (size_t)(EMB + KVD) * EMB, EMB, KVD);
    wsplit_t_kernel<<<dim3(EMB / 32, EMB / 32), dim3(32, 8)>>>(Wo, woh, wol, EMB, EMB);

    // fused QKV projection + RoPE/split epilogue
    gemm_qkv_kernel<<<dim3(QKVN / 128, M / 128), 256, 2 * STAGE_SB>>>(
        xh, xl, wqkvh, wqkvl, EMB, qh, ql, kh, kl, vh, vl, nk, nv, cosT, sinT);

    // attention on tensor cores (BR=128, writes hi/lo split directly)
    flash_mma_kernel<<<dim3(SEQ / 128, BSZ * NH), 256, FSMEM>>>(
        qh, ql, kh, kl, vh, vl, ah, al);

    // output projection on tensor cores
    gemm_mma_kernel<<<dim3(EMB / 128, M / 128), 256, 2 * STAGE_SB>>>(
        ah, al, woh, wol, out, M, EMB, EMB);
}

// round 13
// speedup vs baseline: 1.4103x; 1.1886x over previous
#include <cuda_runtime.h>
#include <cuda_bf16.h>
#include <cuda_fp16.h>
#include <math.h>
#include <stdint.h>

#define BSZ 2
#define SEQ 2048
#define EMB 2048
#define NH  32
#define NKV 8
#define HD  64
#define KVD (NKV * HD)   // 512
#define QKVN (EMB + 2 * KVD)   // 3072

// ---------------- scratch (static device memory; no allocs allowed) ----------
__device__ __nv_bfloat16 g_x_hi[BSZ * SEQ * EMB];
__device__ __nv_bfloat16 g_x_lo[BSZ * SEQ * EMB];
__device__ __half        g_af[BSZ * SEQ * EMB];     // attn out fp16 (B,S,H,D)
__device__ __nv_bfloat16 g_qh[BSZ * SEQ * EMB];     // rope'd q hi (B,H,S,D)
__device__ __nv_bfloat16 g_ql[BSZ * SEQ * EMB];
__device__ __nv_bfloat16 g_kh[BSZ * SEQ * KVD];     // rope'd k hi (B,KV,S,D)
__device__ __nv_bfloat16 g_kl[BSZ * SEQ * KVD];
__device__ __nv_bfloat16 g_vh[BSZ * SEQ * KVD];     // v hi (B,KV,S,D)
__device__ __nv_bfloat16 g_vl[BSZ * SEQ * KVD];
__device__ __nv_bfloat16 g_wqkv_h[QKVN * EMB];      // packed [Wq;Wk;Wv]^T hi
__device__ __nv_bfloat16 g_wqkv_l[QKVN * EMB];
__device__ __half        g_wo_f[EMB * EMB];         // Wo^T fp16

// ======================= helpers =============================================
__device__ __forceinline__ uint32_t cvta_smem(const void* p) {
    uint32_t a;
    asm("{ .reg .u64 t; cvta.to.shared.u64 t, %1; cvt.u32.u64 %0, t; }"
        : "=r"(a) : "l"(p));
    return a;
}

__device__ __forceinline__ void cp16(uint32_t dst, const void* src) {
    asm volatile("cp.async.cg.shared.global [%0], [%1], 16;"
                 :: "r"(dst), "l"(src) : "memory");
}
#define CP_COMMIT() asm volatile("cp.async.commit_group;" ::: "memory")
#define CP_WAIT(n)  asm volatile("cp.async.wait_group %0;" :: "n"(n) : "memory")

__device__ __forceinline__ void ldsm_x4(uint32_t& r0, uint32_t& r1,
                                        uint32_t& r2, uint32_t& r3, uint32_t addr) {
    asm volatile("ldmatrix.sync.aligned.m8n8.x4.shared.b16 {%0,%1,%2,%3}, [%4];"
                 : "=r"(r0), "=r"(r1), "=r"(r2), "=r"(r3) : "r"(addr));
}

__device__ __forceinline__ void ldsm_x4_t(uint32_t& r0, uint32_t& r1,
                                          uint32_t& r2, uint32_t& r3, uint32_t addr) {
    asm volatile("ldmatrix.sync.aligned.m8n8.x4.trans.shared.b16 {%0,%1,%2,%3}, [%4];"
                 : "=r"(r0), "=r"(r1), "=r"(r2), "=r"(r3) : "r"(addr));
}

__device__ __forceinline__ void mma_bf16(float& d0, float& d1, float& d2, float& d3,
                                         uint32_t a0, uint32_t a1, uint32_t a2, uint32_t a3,
                                         uint32_t b0, uint32_t b1) {
    asm volatile(
        "mma.sync.aligned.m16n8k16.row.col.f32.bf16.bf16.f32 "
        "{%0,%1,%2,%3}, {%4,%5,%6,%7}, {%8,%9}, {%0,%1,%2,%3};"
        : "+f"(d0), "+f"(d1), "+f"(d2), "+f"(d3)
        : "r"(a0), "r"(a1), "r"(a2), "r"(a3), "r"(b0), "r"(b1));
}

__device__ __forceinline__ void mma_f16(float& d0, float& d1, float& d2, float& d3,
                                        uint32_t a0, uint32_t a1, uint32_t a2, uint32_t a3,
                                        uint32_t b0, uint32_t b1) {
    asm volatile(
        "mma.sync.aligned.m16n8k16.row.col.f32.f16.f16.f32 "
        "{%0,%1,%2,%3}, {%4,%5,%6,%7}, {%8,%9}, {%0,%1,%2,%3};"
        : "+f"(d0), "+f"(d1), "+f"(d2), "+f"(d3)
        : "r"(a0), "r"(a1), "r"(a2), "r"(a3), "r"(b0), "r"(b1));
}

__device__ __forceinline__ uint32_t pack_bf16(float a, float b) {
    __nv_bfloat162 t(__float2bfloat16(a), __float2bfloat16(b));
    return *(uint32_t*)&t;
}

// ============ split conversion: fp32 -> (hi bf16, lo bf16) ===================
__global__ void split_kernel(const float4* __restrict__ in,
                             __nv_bfloat16* __restrict__ hi,
                             __nv_bfloat16* __restrict__ lo)
{
    int i = blockIdx.x * blockDim.x + threadIdx.x;
    float4 v = in[i];
    __nv_bfloat16 h[4], l[4];
    h[0] = __float2bfloat16(v.x); l[0] = __float2bfloat16(v.x - __bfloat162float(h[0]));
    h[1] = __float2bfloat16(v.y); l[1] = __float2bfloat16(v.y - __bfloat162float(h[1]));
    h[2] = __float2bfloat16(v.z); l[2] = __float2bfloat16(v.z - __bfloat162float(h[2]));
    h[3] = __float2bfloat16(v.w); l[3] = __float2bfloat16(v.w - __bfloat162float(h[3]));
    *(uint2*)&hi[(size_t)i * 4] = *(uint2*)h;
    *(uint2*)&lo[(size_t)i * 4] = *(uint2*)l;
}

// ===== weight transpose + split: W[K,N] fp32 -> Wt_hi/lo [N,K] bf16 ==========
__global__ void wsplit_t_kernel(const float* __restrict__ W,
                                __nv_bfloat16* __restrict__ Th,
                                __nv_bfloat16* __restrict__ Tl,
                                int K, int N)
{
    __shared__ float tile[32][33];
    int n0 = blockIdx.x * 32, k0 = blockIdx.y * 32;
    int tx = threadIdx.x, ty = threadIdx.y;   // 32 x 8
#pragma unroll
    for (int i = 0; i < 4; i++)
        tile[ty + 8 * i][tx] = W[(size_t)(k0 + ty + 8 * i) * N + n0 + tx];
    __syncthreads();
#pragma unroll
    for (int i = 0; i < 4; i++) {
        float v = tile[tx][ty + 8 * i];
        __nv_bfloat16 h = __float2bfloat16(v);
        __nv_bfloat16 l = __float2bfloat16(v - __bfloat162float(h));
        size_t o = (size_t)(n0 + ty + 8 * i) * K + k0 + tx;
        Th[o] = h;
        Tl[o] = l;
    }
}

// ===== weight transpose fp16: W[K,N] fp32 -> Wt [N,K] fp16 ===================
__global__ void wt_f16_kernel(const float* __restrict__ W,
                              __half* __restrict__ T, int K, int N)
{
    __shared__ float tile[32][33];
    int n0 = blockIdx.x * 32, k0 = blockIdx.y * 32;
    int tx = threadIdx.x, ty = threadIdx.y;
#pragma unroll
    for (int i = 0; i < 4; i++)
        tile[ty + 8 * i][tx] = W[(size_t)(k0 + ty + 8 * i) * N + n0 + tx];
    __syncthreads();
#pragma unroll
    for (int i = 0; i < 4; i++)
        T[(size_t)(n0 + ty + 8 * i) * K + k0 + tx] = __float2half(tile[tx][ty + 8 * i]);
}

// ====== shared GEMM mainloop config (BK=32, 80KB smem -> 2 CTAs/SM) ==========
#define ROWB 80
#define TILE_SB (128 * ROWB)
#define STAGE_SB (4 * TILE_SB)

__device__ __forceinline__ void gemm_mainloop(
    const __nv_bfloat16* __restrict__ Ah, const __nv_bfloat16* __restrict__ Al,
    const __nv_bfloat16* __restrict__ Bh, const __nv_bfloat16* __restrict__ Bl,
    int K, int mT, int nT, char* dsm, float acc[4][4][4])
{
    const int tid = threadIdx.x;
    const int wid = tid >> 5, lane = tid & 31;
    const int wm = wid >> 2, wn = wid & 3;
    const uint32_t sbase = cvta_smem(dsm);

    const int gr  = tid >> 1;
    const int gk  = (tid & 1) * 2;
    const __nv_bfloat16* srcs[4] = {
        Ah + (size_t)(mT * 128 + gr) * K + gk * 8,
        Al + (size_t)(mT * 128 + gr) * K + gk * 8,
        Bh + (size_t)(nT * 128 + gr) * K + gk * 8,
        Bl + (size_t)(nT * 128 + gr) * K + gk * 8
    };
    const uint32_t sdst = gr * ROWB + gk * 16;

#pragma unroll
    for (int i = 0; i < 4; i++)
#pragma unroll
        for (int j = 0; j < 4; j++)
#pragma unroll
            for (int v = 0; v < 4; v++) acc[i][j][v] = 0.f;

    const int l8 = lane & 7, mi = lane >> 3;
    const uint32_t a_off = (uint32_t)(wm * 64 + l8 + ((mi & 1) << 3)) * ROWB
                         + ((mi >> 1) << 3) * 2;
    const uint32_t b_off = (uint32_t)(wn * 32 + l8 + ((mi & 1) << 3)) * ROWB
                         + ((mi >> 1) << 3) * 2;

    const int nch = K >> 5;

#pragma unroll
    for (int t = 0; t < 4; t++) {
        uint32_t a = sbase + t * TILE_SB + sdst;
        cp16(a, srcs[t]);
        cp16(a + 16, srcs[t] + 8);
    }
    CP_COMMIT();

    for (int ch = 0; ch < nch; ch++) {
        const uint32_t stage = sbase + (ch & 1) * STAGE_SB;
        const bool more = (ch + 1 < nch);

        if (more) {
            const int k0 = (ch + 1) << 5;
            const uint32_t nstage = sbase + ((ch + 1) & 1) * STAGE_SB;
#pragma unroll
            for (int t = 0; t < 4; t++) {
                uint32_t a = nstage + t * TILE_SB + sdst;
                cp16(a, srcs[t] + k0);
                cp16(a + 16, srcs[t] + k0 + 8);
            }
            CP_COMMIT();
            CP_WAIT(1);
        } else {
            CP_WAIT(0);
        }
        __syncthreads();

#pragma unroll
        for (int k16 = 0; k16 < 2; k16++) {
            const uint32_t kb = k16 * 32;
            uint32_t ah[4][4], al[4][4];
#pragma unroll
            for (int i = 0; i < 4; i++) {
                uint32_t addr = stage + a_off + (uint32_t)(i * 16) * ROWB + kb;
                ldsm_x4(ah[i][0], ah[i][1], ah[i][2], ah[i][3], addr);
                ldsm_x4(al[i][0], al[i][1], al[i][2], al[i][3], addr + TILE_SB);
            }
            uint32_t bh[4][2], bl[4][2];
#pragma unroll
            for (int p = 0; p < 2; p++) {
                uint32_t addr = stage + 2 * TILE_SB + b_off + (uint32_t)(p * 16) * ROWB + kb;
                uint32_t r0, r1, r2, r3;
                ldsm_x4(r0, r1, r2, r3, addr);
                bh[2 * p][0] = r0; bh[2 * p][1] = r2;
                bh[2 * p + 1][0] = r1; bh[2 * p + 1][1] = r3;
                ldsm_x4(r0, r1, r2, r3, addr + TILE_SB);
                bl[2 * p][0] = r0; bl[2 * p][1] = r2;
                bl[2 * p + 1][0] = r1; bl[2 * p + 1][1] = r3;
            }
#pragma unroll
            for (int i = 0; i < 4; i++)
#pragma unroll
                for (int j = 0; j < 4; j++) {
                    float* d = acc[i][j];
                    mma_bf16(d[0], d[1], d[2], d[3],
                             ah[i][0], ah[i][1], ah[i][2], ah[i][3],
                             bh[j][0], bh[j][1]);
                    mma_bf16(d[0], d[1], d[2], d[3],
                             ah[i][0], ah[i][1], ah[i][2], ah[i][3],
                             bl[j][0], bl[j][1]);
                    mma_bf16(d[0], d[1], d[2], d[3],
                             al[i][0], al[i][1], al[i][2], al[i][3],
                             bh[j][0], bh[j][1]);
                }
        }
        __syncthreads();
    }
}

// ------- QKV GEMM with fused RoPE/vtrans/split epilogue ----------------------
#define CTP 132   // smem C-tile pitch (floats)

__global__ void __launch_bounds__(256) gemm_qkv_kernel(
    const __nv_bfloat16* __restrict__ Ah, const __nv_bfloat16* __restrict__ Al,
    const __nv_bfloat16* __restrict__ Bh, const __nv_bfloat16* __restrict__ Bl,
    int K,
    __nv_bfloat16* __restrict__ qh, __nv_bfloat16* __restrict__ ql,
    __nv_bfloat16* __restrict__ kh, __nv_bfloat16* __restrict__ kl,
    __nv_bfloat16* __restrict__ vh, __nv_bfloat16* __restrict__ vl,
    float* __restrict__ nk, float* __restrict__ nv,
    const float* __restrict__ cosT, const float* __restrict__ sinT)
{
    extern __shared__ char dsm[];
    const int mT = blockIdx.y, nT = blockIdx.x;
    float acc[4][4][4];
    gemm_mainloop(Ah, Al, Bh, Bl, K, mT, nT, dsm, acc);

    const int tid = threadIdx.x;
    const int wid = tid >> 5, lane = tid & 31;
    const int wm = wid >> 2, wn = wid & 3;
    const int er = lane >> 2, ec = (lane & 3) * 2;
    float* Ct = (float*)dsm;
#pragma unroll
    for (int i = 0; i < 4; i++) {
        const int r0 = wm * 64 + i * 16 + er;
#pragma unroll
        for (int j = 0; j < 4; j++) {
            const int c = wn * 32 + j * 8 + ec;
            Ct[r0 * CTP + c]           = acc[i][j][0];
            Ct[r0 * CTP + c + 1]       = acc[i][j][1];
            Ct[(r0 + 8) * CTP + c]     = acc[i][j][2];
            Ct[(r0 + 8) * CTP + c + 1] = acc[i][j][3];
        }
    }
    __syncthreads();

    if (nT < 20) {
        const bool isQ = (nT < 16);
#pragma unroll 4
        for (int it = 0; it < 32; it++) {
            const int p  = tid + (it << 8);
            const int d  = p & 31;
            const int hd = (p >> 5) & 1;
            const int r  = p >> 6;
            const int gm = mT * 128 + r;
            const int b = gm >> 11, s = gm & 2047;
            const float cv = cosT[s * HD + d];
            const float sv = sinT[s * HD + d];
            const float x1 = Ct[r * CTP + hd * 64 + d];
            const float x2 = Ct[r * CTP + hd * 64 + d + 32];
            const float v1 = x1 * cv - x2 * sv;
            const float v2 = x2 * cv + x1 * sv;
            const __nv_bfloat16 h1 = __float2bfloat16(v1);
            const __nv_bfloat16 h2 = __float2bfloat16(v2);
            const __nv_bfloat16 l1 = __float2bfloat16(v1 - __bfloat162float(h1));
            const __nv_bfloat16 l2 = __float2bfloat16(v2 - __bfloat162float(h2));
            if (isQ) {
                const int h = nT * 2 + hd;
                const size_t o0 = ((size_t)(b * NH + h) * SEQ + s) * HD + d;
                qh[o0] = h1; qh[o0 + 32] = h2;
                ql[o0] = l1; ql[o0 + 32] = l2;
            } else {
                const int kvh = (nT - 16) * 2 + hd;
                const size_t o0 = ((size_t)(b * NKV + kvh) * SEQ + s) * HD + d;
                nk[o0] = v1; nk[o0 + 32] = v2;
                kh[o0] = h1; kh[o0 + 32] = h2;
                kl[o0] = l1; kl[o0 + 32] = l2;
            }
        }
    } else {
        const int c4 = (tid & 31) * 4;
        const int rr = tid >> 5;
        const int hd = c4 >> 6;
        const int d4 = c4 & 63;
        const int kvh = (nT - 20) * 2 + hd;
#pragma unroll 4
        for (int i = 0; i < 16; i++) {
            const int r = rr + i * 8;
            const int gm = mT * 128 + r;
            const int b = gm >> 11, s = gm & 2047;
            float4 v = *(float4*)&Ct[r * CTP + c4];
            const size_t o = ((size_t)(b * NKV + kvh) * SEQ + s) * HD + d4;
            *(float4*)&nv[o] = v;
            __nv_bfloat16 hh[4], ll[4];
            hh[0] = __float2bfloat16(v.x); ll[0] = __float2bfloat16(v.x - __bfloat162float(hh[0]));
            hh[1] = __float2bfloat16(v.y); ll[1] = __float2bfloat16(v.y - __bfloat162float(hh[1]));
            hh[2] = __float2bfloat16(v.z); ll[2] = __float2bfloat16(v.z - __bfloat162float(hh[2]));
            hh[3] = __float2bfloat16(v.w); ll[3] = __float2bfloat16(v.w - __bfloat162float(hh[3]));
            *(uint2*)&vh[o] = *(uint2*)hh;
            *(uint2*)&vl[o] = *(uint2*)ll;
        }
    }
}

// -------- fp16 single-term GEMM (Wo): C[M,N] = A[M,K] @ Bt[N,K]^T ------------
// 2 tiles/stage (20 KB), 2 stages = 40 KB. 256 threads, warp tile 64x32.
#define F16_STAGE (2 * TILE_SB)

__global__ void __launch_bounds__(256) gemm_f16_kernel(
    const __half* __restrict__ A, const __half* __restrict__ Bt,
    float* __restrict__ C, int M, int N, int K)
{
    extern __shared__ char dsm[];
    const int tid = threadIdx.x;
    const int wid = tid >> 5, lane = tid & 31;
    const int wm = wid >> 2, wn = wid & 3;
    const int mT = blockIdx.y, nT = blockIdx.x;
    const uint32_t sbase = cvta_smem(dsm);

    const int gr  = tid >> 1;
    const int gk  = (tid & 1) * 2;
    const __half* srcs[2] = {
        A  + (size_t)(mT * 128 + gr) * K + gk * 8,
        Bt + (size_t)(nT * 128 + gr) * K + gk * 8
    };
    const uint32_t sdst = gr * ROWB + gk * 16;

    float acc[4][4][4];
#pragma unroll
    for (int i = 0; i < 4; i++)
#pragma unroll
        for (int j = 0; j < 4; j++)
#pragma unroll
            for (int v = 0; v < 4; v++) acc[i][j][v] = 0.f;

    const int l8 = lane & 7, mi = lane >> 3;
    const uint32_t a_off = (uint32_t)(wm * 64 + l8 + ((mi & 1) << 3)) * ROWB
                         + ((mi >> 1) << 3) * 2;
    const uint32_t b_off = (uint32_t)(wn * 32 + l8 + ((mi & 1) << 3)) * ROWB
                         + ((mi >> 1) << 3) * 2;

    const int nch = K >> 5;

#pragma unroll
    for (int t = 0; t < 2; t++) {
        uint32_t a = sbase + t * TILE_SB + sdst;
        cp16(a, srcs[t]);
        cp16(a + 16, srcs[t] + 8);
    }
    CP_COMMIT();

    for (int ch = 0; ch < nch; ch++) {
        const uint32_t stage = sbase + (ch & 1) * F16_STAGE;
        const bool more = (ch + 1 < nch);

        if (more) {
            const int k0 = (ch + 1) << 5;
            const uint32_t nstage = sbase + ((ch + 1) & 1) * F16_STAGE;
#pragma unroll
            for (int t = 0; t < 2; t++) {
                uint32_t a = nstage + t * TILE_SB + sdst;
                cp16(a, srcs[t] + k0);
                cp16(a + 16, srcs[t] + k0 + 8);
            }
            CP_COMMIT();
            CP_WAIT(1);
        } else {
            CP_WAIT(0);
        }
        __syncthreads();

#pragma unroll
        for (int k16 = 0; k16 < 2; k16++) {
            const uint32_t kb = k16 * 32;
            uint32_t af[4][4];
#pragma unroll
            for (int i = 0; i < 4; i++) {
                uint32_t addr = stage + a_off + (uint32_t)(i * 16) * ROWB + kb;
                ldsm_x4(af[i][0], af[i][1], af[i][2], af[i][3], addr);
            }
            uint32_t bf[4][2];
#pragma unroll
            for (int p = 0; p < 2; p++) {
                uint32_t addr = stage + TILE_SB + b_off + (uint32_t)(p * 16) * ROWB + kb;
                uint32_t r0, r1, r2, r3;
                ldsm_x4(r0, r1, r2, r3, addr);
                bf[2 * p][0] = r0; bf[2 * p][1] = r2;
                bf[2 * p + 1][0] = r1; bf[2 * p + 1][1] = r3;
            }
#pragma unroll
            for (int i = 0; i < 4; i++)
#pragma unroll
                for (int j = 0; j < 4; j++)
                    mma_f16(acc[i][j][0], acc[i][j][1], acc[i][j][2], acc[i][j][3],
                            af[i][0], af[i][1], af[i][2], af[i][3],
                            bf[j][0], bf[j][1]);
        }
        __syncthreads();
    }

    const int er = lane >> 2, ec = (lane & 3) * 2;
    float* Cb = C + (size_t)(mT * 128 + wm * 64 + er) * N + nT * 128 + wn * 32 + ec;
#pragma unroll
    for (int i = 0; i < 4; i++)
#pragma unroll
        for (int j = 0; j < 4; j++) {
            float* p0 = Cb + (size_t)(i * 16) * N + j * 8;
            *(float2*)p0                      = make_float2(acc[i][j][0], acc[i][j][1]);
            *(float2*)(p0 + (size_t)8 * N)    = make_float2(acc[i][j][2], acc[i][j][3]);
        }
}

// ---------------- causal flash attention (mma.sync bf16 split) ---------------
// BR=128 (8 warps x 16 rows), BC=64, 256 threads. Output: fp16 (B,S,H,D).
#define FROWB  144
#define FQTILE (128 * FROWB)
#define FKTILE (64 * FROWB)
#define FSMEM  (2 * FQTILE + 4 * FKTILE)   // 73728

__global__ void __launch_bounds__(256) flash_mma_kernel(
    const __nv_bfloat16* __restrict__ Qh, const __nv_bfloat16* __restrict__ Ql,
    const __nv_bfloat16* __restrict__ Kh, const __nv_bfloat16* __restrict__ Kl,
    const __nv_bfloat16* __restrict__ Vh, const __nv_bfloat16* __restrict__ Vl,
    __half* __restrict__ O)
{
    extern __shared__ char fsm[];
    const uint32_t sb  = cvta_smem(fsm);
    const uint32_t sQh = sb, sQl = sb + FQTILE;
    const uint32_t sKh = sb + 2 * FQTILE;
    const uint32_t sKl = sKh + FKTILE;
    const uint32_t sVh = sKh + 2 * FKTILE;
    const uint32_t sVl = sKh + 3 * FKTILE;

    const int qt = blockIdx.x, hh = blockIdx.y;
    const int b = hh >> 5, h = hh & 31, kvh = h >> 2;
    const int tid = threadIdx.x, wid = tid >> 5, lane = tid & 31;

    const __nv_bfloat16* Qhb = Qh + ((size_t)((b * NH + h) * SEQ) + qt * 128) * HD;
    const __nv_bfloat16* Qlb = Ql + ((size_t)((b * NH + h) * SEQ) + qt * 128) * HD;
    const __nv_bfloat16* Khb = Kh + (size_t)((b * NKV + kvh) * SEQ) * HD;
    const __nv_bfloat16* Klb = Kl + (size_t)((b * NKV + kvh) * SEQ) * HD;
    const __nv_bfloat16* Vhb = Vh + (size_t)((b * NKV + kvh) * SEQ) * HD;
    const __nv_bfloat16* Vlb = Vl + (size_t)((b * NKV + kvh) * SEQ) * HD;

    {
        const int r = tid >> 1, hf = tid & 1;
        const uint4* s0 = (const uint4*)(Qhb + (size_t)r * HD + hf * 32);
        const uint4* s1 = (const uint4*)(Qlb + (size_t)r * HD + hf * 32);
        uint32_t d0 = sQh + r * FROWB + hf * 64;
        uint32_t d1 = sQl + r * FROWB + hf * 64;
#pragma unroll
        for (int i = 0; i < 4; i++) {
            uint4 v = s0[i];
            asm volatile("st.shared.v4.b32 [%0], {%1,%2,%3,%4};"
                         :: "r"(d0 + i * 16), "r"(v.x), "r"(v.y), "r"(v.z), "r"(v.w) : "memory");
            v = s1[i];
            asm volatile("st.shared.v4.b32 [%0], {%1,%2,%3,%4};"
                         :: "r"(d1 + i * 16), "r"(v.x), "r"(v.y), "r"(v.z), "r"(v.w) : "memory");
        }
    }

    const int l8 = lane & 7, mi = lane >> 3;
    const uint32_t qa_off = (uint32_t)(wid * 16 + l8 + ((mi & 1) << 3)) * FROWB
                          + ((mi >> 1) << 4);
    const uint32_t kb_base = (uint32_t)(l8 + ((mi & 1) << 3)) * FROWB + ((mi >> 1) << 4);
    const uint32_t vb_base = (uint32_t)(((mi & 1) << 3) + l8) * FROWB + ((mi >> 1) << 4);

    float m0 = -1e30f, m1 = -1e30f, l0 = 0.f, l1 = 0.f;
    float o[8][4];
#pragma unroll
    for (int j = 0; j < 8; j++)
#pragma unroll
        for (int v = 0; v < 4; v++) o[j][v] = 0.f;

    const int rlo = wid * 16 + (lane >> 2);
    const int rhi = rlo + 8;

    const int ntiles = 2 * qt + 2;
    for (int kt = 0; kt < ntiles; kt++) {
        __syncthreads();
        {
            const int r = tid >> 2, q4 = tid & 3;
            const size_t goff = (size_t)(kt * 64 + r) * HD + q4 * 16;
            const uint32_t dof = r * FROWB + q4 * 32;
            const __nv_bfloat16* gs[4] = { Khb + goff, Klb + goff, Vhb + goff, Vlb + goff };
            const uint32_t ds[4] = { sKh + dof, sKl + dof, sVh + dof, sVl + dof };
#pragma unroll
            for (int t = 0; t < 4; t++) {
                uint4 v0 = *(const uint4*)(gs[t]);
                uint4 v1 = *(const uint4*)(gs[t] + 8);
                asm volatile("st.shared.v4.b32 [%0], {%1,%2,%3,%4};"
                             :: "r"(ds[t]), "r"(v0.x), "r"(v0.y), "r"(v0.z), "r"(v0.w) : "memory");
                asm volatile("st.shared.v4.b32 [%0], {%1,%2,%3,%4};"
                             :: "r"(ds[t] + 16), "r"(v1.x), "r"(v1.y), "r"(v1.z), "r"(v1.w) : "memory");
            }
        }
        __syncthreads();

        float sa[8][4];
#pragma unroll
        for (int j = 0; j < 8; j++)
#pragma unroll
            for (int v = 0; v < 4; v++) sa[j][v] = 0.f;

#pragma unroll
        for (int ks = 0; ks < 4; ks++) {
            uint32_t aqh[4], aql[4];
            ldsm_x4(aqh[0], aqh[1], aqh[2], aqh[3], sQh + qa_off + ks * 32);
            ldsm_x4(aql[0], aql[1], aql[2], aql[3], sQl + qa_off + ks * 32);
#pragma unroll
            for (int p = 0; p < 4; p++) {
                uint32_t addr = kb_base + (uint32_t)(p * 16) * FROWB + ks * 32;
                uint32_t r0, r1, r2, r3;
                uint32_t bh0[2], bh1[2], bl0[2], bl1[2];
                ldsm_x4(r0, r1, r2, r3, sKh + addr);
                bh0[0] = r0; bh0[1] = r2; bh1[0] = r1; bh1[1] = r3;
                ldsm_x4(r0, r1, r2, r3, sKl + addr);
                bl0[0] = r0; bl0[1] = r2; bl1[0] = r1; bl1[1] = r3;
                float* d0 = sa[2 * p];
                float* d1 = sa[2 * p + 1];
                mma_bf16(d0[0], d0[1], d0[2], d0[3], aqh[0], aqh[1], aqh[2], aqh[3], bh0[0], bh0[1]);
                mma_bf16(d0[0], d0[1], d0[2], d0[3], aqh[0], aqh[1], aqh[2], aqh[3], bl0[0], bl0[1]);
                mma_bf16(d0[0], d0[1], d0[2], d0[3], aql[0], aql[1], aql[2], aql[3], bh0[0], bh0[1]);
                mma_bf16(d1[0], d1[1], d1[2], d1[3], aqh[0], aqh[1], aqh[2], aqh[3], bh1[0], bh1[1]);
                mma_bf16(d1[0], d1[1], d1[2], d1[3], aqh[0], aqh[1], aqh[2], aqh[3], bl1[0], bl1[1]);
                mma_bf16(d1[0], d1[1], d1[2], d1[3], aql[0], aql[1], aql[2], aql[3], bh1[0], bh1[1]);
            }
        }

        const int ktd = kt - 2 * qt;
        float mx0 = -1e30f, mx1 = -1e30f;
#pragma unroll
        for (int j = 0; j < 8; j++) {
            const int c0 = 8 * j + (lane & 3) * 2;
#pragma unroll
            for (int v = 0; v < 4; v++) {
                float sc = sa[j][v] * 0.125f;
                if (ktd >= 0) {
                    int col = c0 + (v & 1) + (ktd << 6);
                    int row = (v < 2) ? rlo : rhi;
                    if (col > row) sc = -1e30f;
                }
                sa[j][v] = sc;
            }
            mx0 = fmaxf(mx0, fmaxf(sa[j][0], sa[j][1]));
            mx1 = fmaxf(mx1, fmaxf(sa[j][2], sa[j][3]));
        }
        mx0 = fmaxf(mx0, __shfl_xor_sync(0xffffffffu, mx0, 1));
        mx0 = fmaxf(mx0, __shfl_xor_sync(0xffffffffu, mx0, 2));
        mx1 = fmaxf(mx1, __shfl_xor_sync(0xffffffffu, mx1, 1));
        mx1 = fmaxf(mx1, __shfl_xor_sync(0xffffffffu, mx1, 2));

        const float mn0 = fmaxf(m0, mx0), mn1 = fmaxf(m1, mx1);
        const float al0 = __expf(m0 - mn0), al1 = __expf(m1 - mn1);
        m0 = mn0; m1 = mn1;

        float sum0 = 0.f, sum1 = 0.f;
#pragma unroll
        for (int j = 0; j < 8; j++) {
            float e0 = __expf(sa[j][0] - mn0);
            float e1 = __expf(sa[j][1] - mn0);
            float e2 = __expf(sa[j][2] - mn1);
            float e3 = __expf(sa[j][3] - mn1);
            sa[j][0] = e0; sa[j][1] = e1; sa[j][2] = e2; sa[j][3] = e3;
            sum0 += e0 + e1;
            sum1 += e2 + e3;
        }
        sum0 += __shfl_xor_sync(0xffffffffu, sum0, 1);
        sum0 += __shfl_xor_sync(0xffffffffu, sum0, 2);
        sum1 += __shfl_xor_sync(0xffffffffu, sum1, 1);
        sum1 += __shfl_xor_sync(0xffffffffu, sum1, 2);
        l0 = l0 * al0 + sum0;
        l1 = l1 * al1 + sum1;

#pragma unroll
        for (int j = 0; j < 8; j++) {
            o[j][0] *= al0; o[j][1] *= al0;
            o[j][2] *= al1; o[j][3] *= al1;
        }

#pragma unroll
        for (int kc = 0; kc < 4; kc++) {
            const float* e0 = sa[2 * kc];
            const float* e1 = sa[2 * kc + 1];
            uint32_t ph[4], pl[4];
            ph[0] = pack_bf16(e0[0], e0[1]);
            ph[1] = pack_bf16(e0[2], e0[3]);
            ph[2] = pack_bf16(e1[0], e1[1]);
            ph[3] = pack_bf16(e1[2], e1[3]);
            {
                __nv_bfloat162 t;
                t = *(__nv_bfloat162*)&ph[0];
                pl[0] = pack_bf16(e0[0] - __bfloat162float(t.x), e0[1] - __bfloat162float(t.y));
                t = *(__nv_bfloat162*)&ph[1];
                pl[1] = pack_bf16(e0[2] - __bfloat162float(t.x), e0[3] - __bfloat162float(t.y));
                t = *(__nv_bfloat162*)&ph[2];
                pl[2] = pack_bf16(e1[0] - __bfloat162float(t.x), e1[1] - __bfloat162float(t.y));
                t = *(__nv_bfloat162*)&ph[3];
                pl[3] = pack_bf16(e1[2] - __bfloat162float(t.x), e1[3] - __bfloat162float(t.y));
            }
#pragma unroll
            for (int t4 = 0; t4 < 4; t4++) {
                uint32_t addr = vb_base + (uint32_t)(kc * 16) * FROWB + t4 * 32;
                uint32_t r0, r1, r2, r3;
                uint32_t bh0[2], bh1[2], bl0[2], bl1[2];
                ldsm_x4_t(r0, r1, r2, r3, sVh + addr);
                bh0[0] = r0; bh0[1] = r1; bh1[0] = r2; bh1[1] = r3;
                ldsm_x4_t(r0, r1, r2, r3, sVl + addr);
                bl0[0] = r0; bl0[1] = r1; bl1[0] = r2; bl1[1] = r3;
                float* d0 = o[2 * t4];
                float* d1 = o[2 * t4 + 1];
                mma_bf16(d0[0], d0[1], d0[2], d0[3], ph[0], ph[1], ph[2], ph[3], bh0[0], bh0[1]);
                mma_bf16(d0[0], d0[1], d0[2], d0[3], pl[0], pl[1], pl[2], pl[3], bh0[0], bh0[1]);
                mma_bf16(d0[0], d0[1], d0[2], d0[3], ph[0], ph[1], ph[2], ph[3], bl0[0], bl0[1]);
                mma_bf16(d1[0], d1[1], d1[2], d1[3], ph[0], ph[1], ph[2], ph[3], bh1[0], bh1[1]);
                mma_bf16(d1[0], d1[1], d1[2], d1[3], pl[0], pl[1], pl[2], pl[3], bh1[0], bh1[1]);
                mma_bf16(d1[0], d1[1], d1[2], d1[3], ph[0], ph[1], ph[2], ph[3], bl1[0], bl1[1]);
            }
        }
    }

    // ---- normalize + write fp16 to (B,S,H,D)
    const float inv0 = 1.f / l0, inv1 = 1.f / l1;
    const int glo = qt * 128 + rlo;
    const int ghi = glo + 8;
#pragma unroll
    for (int j = 0; j < 8; j++) {
        const int d = 8 * j + (lane & 3) * 2;
        size_t plo = ((size_t)(b * SEQ + glo) * NH + h) * HD + d;
        size_t phi = ((size_t)(b * SEQ + ghi) * NH + h) * HD + d;
        *(__half2*)&O[plo] = __halves2half2(__float2half(o[j][0] * inv0),
                                            __float2half(o[j][1] * inv0));
        *(__half2*)&O[phi] = __halves2half2(__float2half(o[j][2] * inv1),
                                            __float2half(o[j][3] * inv1));
    }
}

// ---------------- launch -----------------------------------------------------
extern "C" void kernel_launch(void* const* d_in, const int* in_sizes, int n_in,
                              void* d_out, int out_size)
{
    const float* x    = (const float*)d_in[0];
    const float* cosT = (const float*)d_in[2];
    const float* sinT = (const float*)d_in[3];
    const float* Wq   = (const float*)d_in[4];
    const float* Wk   = (const float*)d_in[5];
    const float* Wv   = (const float*)d_in[6];
    const float* Wo   = (const float*)d_in[7];

    float* out = (float*)d_out;                         // (B,S,E)
    float* nk  = out + (size_t)BSZ * SEQ * EMB;         // (B,KV,S,D)
    float* nv  = nk + (size_t)BSZ * NKV * SEQ * HD;     // (B,KV,S,D)

    __nv_bfloat16 *xh, *xl, *qh, *ql, *kh, *kl, *vh, *vl, *wqkvh, *wqkvl;
    __half *af, *wof;
    cudaGetSymbolAddress((void**)&xh,  g_x_hi);
    cudaGetSymbolAddress((void**)&xl,  g_x_lo);
    cudaGetSymbolAddress((void**)&af,  g_af);
    cudaGetSymbolAddress((void**)&qh,  g_qh);
    cudaGetSymbolAddress((void**)&ql,  g_ql);
    cudaGetSymbolAddress((void**)&kh,  g_kh);
    cudaGetSymbolAddress((void**)&kl,  g_kl);
    cudaGetSymbolAddress((void**)&vh,  g_vh);
    cudaGetSymbolAddress((void**)&vl,  g_vl);
    cudaGetSymbolAddress((void**)&wqkvh, g_wqkv_h);
    cudaGetSymbolAddress((void**)&wqkvl, g_wqkv_l);
    cudaGetSymbolAddress((void**)&wof, g_wo_f);

    cudaFuncSetAttribute(gemm_qkv_kernel,
                         cudaFuncAttributeMaxDynamicSharedMemorySize, 2 * STAGE_SB);
    cudaFuncSetAttribute(gemm_f16_kernel,
                         cudaFuncAttributeMaxDynamicSharedMemorySize, 2 * F16_STAGE);
    cudaFuncSetAttribute(flash_mma_kernel,
                         cudaFuncAttributeMaxDynamicSharedMemorySize, FSMEM);

    const int M = BSZ * SEQ;          // 4096
    const size_t NX = (size_t)M * EMB;

    // split x + weights (QKV packed row-wise [3072 x 2048]; Wo fp16)
    split_kernel<<<(int)(NX / 4 / 256), 256>>>((const float4*)x, xh, xl);
    wsplit_t_kernel<<<dim3(EMB / 32, EMB / 32), dim3(32, 8)>>>(Wq, wqkvh, wqkvl, EMB, EMB);
    wsplit_t_kernel<<<dim3(KVD / 32, EMB / 32), dim3(32, 8)>>>(
        Wk, wqkvh + (size_t)EMB * EMB, wqkvl + (size_t)EMB * EMB, EMB, KVD);
    wsplit_t_kernel<<<dim3(KVD / 32, EMB / 32), dim3(32, 8)>>>(
        Wv, wqkvh + (size_t)(EMB + KVD) * EMB, wqkvl + (size_t)(EMB + KVD) * EMB, EMB, KVD);
    wt_f16_kernel<<<dim3(EMB / 32, EMB / 32), dim3(32, 8)>>>(Wo, wof, EMB, EMB);

    // fused QKV projection + RoPE/split epilogue
    gemm_qkv_kernel<<<dim3(QKVN / 128, M / 128), 256, 2 * STAGE_SB>>>(
        xh, xl, wqkvh, wqkvl, EMB, qh, ql, kh, kl, vh, vl, nk, nv, cosT, sinT);

    // attention on tensor cores (BR=128, writes fp16 output)
    flash_mma_kernel<<<dim3(SEQ / 128, BSZ * NH), 256, FSMEM>>>(
        qh, ql, kh, kl, vh, vl, af);

    // output projection: single-term fp16 GEMM
    gemm_f16_kernel<<<dim3(EMB / 128, M / 128), 256, 2 * F16_STAGE>>>(
        af, wof, out, M, EMB, EMB);
}

// round 16
// speedup vs baseline: 1.6544x; 1.1730x over previous
#include <cuda_runtime.h>
#include <cuda_bf16.h>
#include <cuda_fp16.h>
#include <math.h>
#include <stdint.h>

#define BSZ 2
#define SEQ 2048
#define EMB 2048
#define NH  32
#define NKV 8
#define HD  64
#define KVD (NKV * HD)   // 512
#define QKVN (EMB + 2 * KVD)   // 3072

// ---------------- scratch (static device memory; no allocs allowed) ----------
__device__ __half        g_xf_hi[BSZ * SEQ * EMB];  // x fp16 hi
__device__ __half        g_xf_lo[BSZ * SEQ * EMB];  // x fp16 lo (residual)
__device__ __half        g_af[BSZ * SEQ * EMB];     // attn out fp16 (B,S,H,D)
__device__ __nv_bfloat16 g_qh[BSZ * SEQ * EMB];     // rope'd q hi (B,H,S,D)
__device__ __nv_bfloat16 g_ql[BSZ * SEQ * EMB];
__device__ __nv_bfloat16 g_kh[BSZ * SEQ * KVD];     // rope'd k hi (B,KV,S,D)
__device__ __nv_bfloat16 g_kl[BSZ * SEQ * KVD];
__device__ __nv_bfloat16 g_vh[BSZ * SEQ * KVD];     // v hi (B,KV,S,D)
__device__ __nv_bfloat16 g_vl[BSZ * SEQ * KVD];
__device__ __half        g_wqkv_f[QKVN * EMB];      // packed [Wq;Wk;Wv]^T fp16
__device__ __half        g_wo_f[EMB * EMB];         // Wo^T fp16

// ======================= helpers =============================================
__device__ __forceinline__ uint32_t cvta_smem(const void* p) {
    uint32_t a;
    asm("{ .reg .u64 t; cvta.to.shared.u64 t, %1; cvt.u32.u64 %0, t; }"
        : "=r"(a) : "l"(p));
    return a;
}

__device__ __forceinline__ void cp16(uint32_t dst, const void* src) {
    asm volatile("cp.async.cg.shared.global [%0], [%1], 16;"
                 :: "r"(dst), "l"(src) : "memory");
}
#define CP_COMMIT() asm volatile("cp.async.commit_group;" ::: "memory")
#define CP_WAIT(n)  asm volatile("cp.async.wait_group %0;" :: "n"(n) : "memory")

__device__ __forceinline__ void ldsm_x4(uint32_t& r0, uint32_t& r1,
                                        uint32_t& r2, uint32_t& r3, uint32_t addr) {
    asm volatile("ldmatrix.sync.aligned.m8n8.x4.shared.b16 {%0,%1,%2,%3}, [%4];"
                 : "=r"(r0), "=r"(r1), "=r"(r2), "=r"(r3) : "r"(addr));
}

__device__ __forceinline__ void ldsm_x4_t(uint32_t& r0, uint32_t& r1,
                                          uint32_t& r2, uint32_t& r3, uint32_t addr) {
    asm volatile("ldmatrix.sync.aligned.m8n8.x4.trans.shared.b16 {%0,%1,%2,%3}, [%4];"
                 : "=r"(r0), "=r"(r1), "=r"(r2), "=r"(r3) : "r"(addr));
}

__device__ __forceinline__ void mma_bf16(float& d0, float& d1, float& d2, float& d3,
                                         uint32_t a0, uint32_t a1, uint32_t a2, uint32_t a3,
                                         uint32_t b0, uint32_t b1) {
    asm volatile(
        "mma.sync.aligned.m16n8k16.row.col.f32.bf16.bf16.f32 "
        "{%0,%1,%2,%3}, {%4,%5,%6,%7}, {%8,%9}, {%0,%1,%2,%3};"
        : "+f"(d0), "+f"(d1), "+f"(d2), "+f"(d3)
        : "r"(a0), "r"(a1), "r"(a2), "r"(a3), "r"(b0), "r"(b1));
}

__device__ __forceinline__ void mma_f16(float& d0, float& d1, float& d2, float& d3,
                                        uint32_t a0, uint32_t a1, uint32_t a2, uint32_t a3,
                                        uint32_t b0, uint32_t b1) {
    asm volatile(
        "mma.sync.aligned.m16n8k16.row.col.f32.f16.f16.f32 "
        "{%0,%1,%2,%3}, {%4,%5,%6,%7}, {%8,%9}, {%0,%1,%2,%3};"
        : "+f"(d0), "+f"(d1), "+f"(d2), "+f"(d3)
        : "r"(a0), "r"(a1), "r"(a2), "r"(a3), "r"(b0), "r"(b1));
}

__device__ __forceinline__ uint32_t pack_bf16(float a, float b) {
    __nv_bfloat162 t(__float2bfloat16(a), __float2bfloat16(b));
    return *(uint32_t*)&t;
}

// ============ split conversion: fp32 -> (hi fp16, lo fp16) ===================
__global__ void split_f16_kernel(const float4* __restrict__ in,
                                 __half* __restrict__ hi,
                                 __half* __restrict__ lo)
{
    int i = blockIdx.x * blockDim.x + threadIdx.x;
    float4 v = in[i];
    __half h[4], l[4];
    h[0] = __float2half(v.x); l[0] = __float2half(v.x - __half2float(h[0]));
    h[1] = __float2half(v.y); l[1] = __float2half(v.y - __half2float(h[1]));
    h[2] = __float2half(v.z); l[2] = __float2half(v.z - __half2float(h[2]));
    h[3] = __float2half(v.w); l[3] = __float2half(v.w - __half2float(h[3]));
    *(uint2*)&hi[(size_t)i * 4] = *(uint2*)h;
    *(uint2*)&lo[(size_t)i * 4] = *(uint2*)l;
}

// ===== weight transpose fp16: W[K,N] fp32 -> Wt [N,K] fp16 ===================
__global__ void wt_f16_kernel(const float* __restrict__ W,
                              __half* __restrict__ T, int K, int N)
{
    __shared__ float tile[32][33];
    int n0 = blockIdx.x * 32, k0 = blockIdx.y * 32;
    int tx = threadIdx.x, ty = threadIdx.y;
#pragma unroll
    for (int i = 0; i < 4; i++)
        tile[ty + 8 * i][tx] = W[(size_t)(k0 + ty + 8 * i) * N + n0 + tx];
    __syncthreads();
#pragma unroll
    for (int i = 0; i < 4; i++)
        T[(size_t)(n0 + ty + 8 * i) * K + k0 + tx] = __float2half(tile[tx][ty + 8 * i]);
}

// ====== GEMM config (BK=32) ==================================================
#define ROWB 80
#define TILE_SB (128 * ROWB)
#define QKV_STAGE (3 * TILE_SB)     // Ah, Al, B  = 30720
#define F16_STAGE (2 * TILE_SB)     // A, B       = 20480
#define CTP 132                     // smem C-tile pitch (floats)
#define QKV_SMEM (128 * CTP * 4)    // 67584 (>= 2*QKV_STAGE)

// ------- QKV GEMM: 2-term fp16 (xh+xl) x W, fused RoPE/split epilogue -------
// nT 0..15: Q -> rope -> qh/ql. nT 16..19: K -> rope -> nk + kh/kl.
// nT 20..23: V -> nv + vh/vl.
__global__ void __launch_bounds__(256) gemm_qkv_kernel(
    const __half* __restrict__ Ah, const __half* __restrict__ Al,
    const __half* __restrict__ Bt, int K,
    __nv_bfloat16* __restrict__ qh, __nv_bfloat16* __restrict__ ql,
    __nv_bfloat16* __restrict__ kh, __nv_bfloat16* __restrict__ kl,
    __nv_bfloat16* __restrict__ vh, __nv_bfloat16* __restrict__ vl,
    float* __restrict__ nk, float* __restrict__ nv,
    const float* __restrict__ cosT, const float* __restrict__ sinT)
{
    extern __shared__ char dsm[];
    const int mT = blockIdx.y, nT = blockIdx.x;
    const int tid = threadIdx.x;
    const int wid = tid >> 5, lane = tid & 31;
    const int wm = wid >> 2, wn = wid & 3;
    const uint32_t sbase = cvta_smem(dsm);

    const int gr  = tid >> 1;
    const int gk  = (tid & 1) * 2;
    const __half* srcs[3] = {
        Ah + (size_t)(mT * 128 + gr) * K + gk * 8,
        Al + (size_t)(mT * 128 + gr) * K + gk * 8,
        Bt + (size_t)(nT * 128 + gr) * K + gk * 8
    };
    const uint32_t sdst = gr * ROWB + gk * 16;

    float acc[4][4][4];
#pragma unroll
    for (int i = 0; i < 4; i++)
#pragma unroll
        for (int j = 0; j < 4; j++)
#pragma unroll
            for (int v = 0; v < 4; v++) acc[i][j][v] = 0.f;

    const int l8 = lane & 7, mi = lane >> 3;
    const uint32_t a_off = (uint32_t)(wm * 64 + l8 + ((mi & 1) << 3)) * ROWB
                         + ((mi >> 1) << 3) * 2;
    const uint32_t b_off = (uint32_t)(wn * 32 + l8 + ((mi & 1) << 3)) * ROWB
                         + ((mi >> 1) << 3) * 2;

    const int nch = K >> 5;

#pragma unroll
    for (int t = 0; t < 3; t++) {
        uint32_t a = sbase + t * TILE_SB + sdst;
        cp16(a, srcs[t]);
        cp16(a + 16, srcs[t] + 8);
    }
    CP_COMMIT();

    for (int ch = 0; ch < nch; ch++) {
        const uint32_t stage = sbase + (ch & 1) * QKV_STAGE;
        const bool more = (ch + 1 < nch);

        if (more) {
            const int k0 = (ch + 1) << 5;
            const uint32_t nstage = sbase + ((ch + 1) & 1) * QKV_STAGE;
#pragma unroll
            for (int t = 0; t < 3; t++) {
                uint32_t a = nstage + t * TILE_SB + sdst;
                cp16(a, srcs[t] + k0);
                cp16(a + 16, srcs[t] + k0 + 8);
            }
            CP_COMMIT();
            CP_WAIT(1);
        } else {
            CP_WAIT(0);
        }
        __syncthreads();

#pragma unroll
        for (int k16 = 0; k16 < 2; k16++) {
            const uint32_t kb = k16 * 32;
            uint32_t ahr[4][4], alr[4][4];
#pragma unroll
            for (int i = 0; i < 4; i++) {
                uint32_t addr = stage + a_off + (uint32_t)(i * 16) * ROWB + kb;
                ldsm_x4(ahr[i][0], ahr[i][1], ahr[i][2], ahr[i][3], addr);
                ldsm_x4(alr[i][0], alr[i][1], alr[i][2], alr[i][3], addr + TILE_SB);
            }
            uint32_t bf[4][2];
#pragma unroll
            for (int p = 0; p < 2; p++) {
                uint32_t addr = stage + 2 * TILE_SB + b_off + (uint32_t)(p * 16) * ROWB + kb;
                uint32_t r0, r1, r2, r3;
                ldsm_x4(r0, r1, r2, r3, addr);
                bf[2 * p][0] = r0; bf[2 * p][1] = r2;
                bf[2 * p + 1][0] = r1; bf[2 * p + 1][1] = r3;
            }
#pragma unroll
            for (int i = 0; i < 4; i++)
#pragma unroll
                for (int j = 0; j < 4; j++) {
                    float* d = acc[i][j];
                    mma_f16(d[0], d[1], d[2], d[3],
                            ahr[i][0], ahr[i][1], ahr[i][2], ahr[i][3],
                            bf[j][0], bf[j][1]);
                    mma_f16(d[0], d[1], d[2], d[3],
                            alr[i][0], alr[i][1], alr[i][2], alr[i][3],
                            bf[j][0], bf[j][1]);
                }
        }
        __syncthreads();
    }

    // park C tile in smem
    const int er = lane >> 2, ec = (lane & 3) * 2;
    float* Ct = (float*)dsm;
#pragma unroll
    for (int i = 0; i < 4; i++) {
        const int r0 = wm * 64 + i * 16 + er;
#pragma unroll
        for (int j = 0; j < 4; j++) {
            const int c = wn * 32 + j * 8 + ec;
            Ct[r0 * CTP + c]           = acc[i][j][0];
            Ct[r0 * CTP + c + 1]       = acc[i][j][1];
            Ct[(r0 + 8) * CTP + c]     = acc[i][j][2];
            Ct[(r0 + 8) * CTP + c + 1] = acc[i][j][3];
        }
    }
    __syncthreads();

    if (nT < 20) {
        const bool isQ = (nT < 16);
#pragma unroll 4
        for (int it = 0; it < 32; it++) {
            const int p  = tid + (it << 8);
            const int d  = p & 31;
            const int hd = (p >> 5) & 1;
            const int r  = p >> 6;
            const int gm = mT * 128 + r;
            const int b = gm >> 11, s = gm & 2047;
            const float cv = cosT[s * HD + d];
            const float sv = sinT[s * HD + d];
            const float x1 = Ct[r * CTP + hd * 64 + d];
            const float x2 = Ct[r * CTP + hd * 64 + d + 32];
            const float v1 = x1 * cv - x2 * sv;
            const float v2 = x2 * cv + x1 * sv;
            const __nv_bfloat16 h1 = __float2bfloat16(v1);
            const __nv_bfloat16 h2 = __float2bfloat16(v2);
            const __nv_bfloat16 l1 = __float2bfloat16(v1 - __bfloat162float(h1));
            const __nv_bfloat16 l2 = __float2bfloat16(v2 - __bfloat162float(h2));
            if (isQ) {
                const int h = nT * 2 + hd;
                const size_t o0 = ((size_t)(b * NH + h) * SEQ + s) * HD + d;
                qh[o0] = h1; qh[o0 + 32] = h2;
                ql[o0] = l1; ql[o0 + 32] = l2;
            } else {
                const int kvh = (nT - 16) * 2 + hd;
                const size_t o0 = ((size_t)(b * NKV + kvh) * SEQ + s) * HD + d;
                nk[o0] = v1; nk[o0 + 32] = v2;
                kh[o0] = h1; kh[o0 + 32] = h2;
                kl[o0] = l1; kl[o0 + 32] = l2;
            }
        }
    } else {
        const int c4 = (tid & 31) * 4;
        const int rr = tid >> 5;
        const int hd = c4 >> 6;
        const int d4 = c4 & 63;
        const int kvh = (nT - 20) * 2 + hd;
#pragma unroll 4
        for (int i = 0; i < 16; i++) {
            const int r = rr + i * 8;
            const int gm = mT * 128 + r;
            const int b = gm >> 11, s = gm & 2047;
            float4 v = *(float4*)&Ct[r * CTP + c4];
            const size_t o = ((size_t)(b * NKV + kvh) * SEQ + s) * HD + d4;
            *(float4*)&nv[o] = v;
            __nv_bfloat16 hh[4], ll[4];
            hh[0] = __float2bfloat16(v.x); ll[0] = __float2bfloat16(v.x - __bfloat162float(hh[0]));
            hh[1] = __float2bfloat16(v.y); ll[1] = __float2bfloat16(v.y - __bfloat162float(hh[1]));
            hh[2] = __float2bfloat16(v.z); ll[2] = __float2bfloat16(v.z - __bfloat162float(hh[2]));
            hh[3] = __float2bfloat16(v.w); ll[3] = __float2bfloat16(v.w - __bfloat162float(hh[3]));
            *(uint2*)&vh[o] = *(uint2*)hh;
            *(uint2*)&vl[o] = *(uint2*)ll;
        }
    }
}

// -------- fp16 single-term GEMM (Wo): C[M,N] = A[M,K] @ Bt[N,K]^T ------------
__global__ void __launch_bounds__(256) gemm_f16_kernel(
    const __half* __restrict__ A, const __half* __restrict__ Bt,
    float* __restrict__ C, int M, int N, int K)
{
    extern __shared__ char dsm[];
    const int tid = threadIdx.x;
    const int wid = tid >> 5, lane = tid & 31;
    const int wm = wid >> 2, wn = wid & 3;
    const int mT = blockIdx.y, nT = blockIdx.x;
    const uint32_t sbase = cvta_smem(dsm);

    const int gr  = tid >> 1;
    const int gk  = (tid & 1) * 2;
    const __half* srcs[2] = {
        A  + (size_t)(mT * 128 + gr) * K + gk * 8,
        Bt + (size_t)(nT * 128 + gr) * K + gk * 8
    };
    const uint32_t sdst = gr * ROWB + gk * 16;

    float acc[4][4][4];
#pragma unroll
    for (int i = 0; i < 4; i++)
#pragma unroll
        for (int j = 0; j < 4; j++)
#pragma unroll
            for (int v = 0; v < 4; v++) acc[i][j][v] = 0.f;

    const int l8 = lane & 7, mi = lane >> 3;
    const uint32_t a_off = (uint32_t)(wm * 64 + l8 + ((mi & 1) << 3)) * ROWB
                         + ((mi >> 1) << 3) * 2;
    const uint32_t b_off = (uint32_t)(wn * 32 + l8 + ((mi & 1) << 3)) * ROWB
                         + ((mi >> 1) << 3) * 2;

    const int nch = K >> 5;

#pragma unroll
    for (int t = 0; t < 2; t++) {
        uint32_t a = sbase + t * TILE_SB + sdst;
        cp16(a, srcs[t]);
        cp16(a + 16, srcs[t] + 8);
    }
    CP_COMMIT();

    for (int ch = 0; ch < nch; ch++) {
        const uint32_t stage = sbase + (ch & 1) * F16_STAGE;
        const bool more = (ch + 1 < nch);

        if (more) {
            const int k0 = (ch + 1) << 5;
            const uint32_t nstage = sbase + ((ch + 1) & 1) * F16_STAGE;
#pragma unroll
            for (int t = 0; t < 2; t++) {
                uint32_t a = nstage + t * TILE_SB + sdst;
                cp16(a, srcs[t] + k0);
                cp16(a + 16, srcs[t] + k0 + 8);
            }
            CP_COMMIT();
            CP_WAIT(1);
        } else {
            CP_WAIT(0);
        }
        __syncthreads();

#pragma unroll
        for (int k16 = 0; k16 < 2; k16++) {
            const uint32_t kb = k16 * 32;
            uint32_t af[4][4];
#pragma unroll
            for (int i = 0; i < 4; i++) {
                uint32_t addr = stage + a_off + (uint32_t)(i * 16) * ROWB + kb;
                ldsm_x4(af[i][0], af[i][1], af[i][2], af[i][3], addr);
            }
            uint32_t bf[4][2];
#pragma unroll
            for (int p = 0; p < 2; p++) {
                uint32_t addr = stage + TILE_SB + b_off + (uint32_t)(p * 16) * ROWB + kb;
                uint32_t r0, r1, r2, r3;
                ldsm_x4(r0, r1, r2, r3, addr);
                bf[2 * p][0] = r0; bf[2 * p][1] = r2;
                bf[2 * p + 1][0] = r1; bf[2 * p + 1][1] = r3;
            }
#pragma unroll
            for (int i = 0; i < 4; i++)
#pragma unroll
                for (int j = 0; j < 4; j++)
                    mma_f16(acc[i][j][0], acc[i][j][1], acc[i][j][2], acc[i][j][3],
                            af[i][0], af[i][1], af[i][2], af[i][3],
                            bf[j][0], bf[j][1]);
        }
        __syncthreads();
    }

    const int er = lane >> 2, ec = (lane & 3) * 2;
    float* Cb = C + (size_t)(mT * 128 + wm * 64 + er) * N + nT * 128 + wn * 32 + ec;
#pragma unroll
    for (int i = 0; i < 4; i++)
#pragma unroll
        for (int j = 0; j < 4; j++) {
            float* p0 = Cb + (size_t)(i * 16) * N + j * 8;
            *(float2*)p0                      = make_float2(acc[i][j][0], acc[i][j][1]);
            *(float2*)(p0 + (size_t)8 * N)    = make_float2(acc[i][j][2], acc[i][j][3]);
        }
}

// ---------------- causal flash attention (mma.sync bf16 split) ---------------
// BR=128 (8 warps x 16 rows), BC=64, 256 threads. Output: fp16 (B,S,H,D).
#define FROWB  144
#define FQTILE (128 * FROWB)
#define FKTILE (64 * FROWB)
#define FSMEM  (2 * FQTILE + 4 * FKTILE)   // 73728

__global__ void __launch_bounds__(256) flash_mma_kernel(
    const __nv_bfloat16* __restrict__ Qh, const __nv_bfloat16* __restrict__ Ql,
    const __nv_bfloat16* __restrict__ Kh, const __nv_bfloat16* __restrict__ Kl,
    const __nv_bfloat16* __restrict__ Vh, const __nv_bfloat16* __restrict__ Vl,
    __half* __restrict__ O)
{
    extern __shared__ char fsm[];
    const uint32_t sb  = cvta_smem(fsm);
    const uint32_t sQh = sb, sQl = sb + FQTILE;
    const uint32_t sKh = sb + 2 * FQTILE;
    const uint32_t sKl = sKh + FKTILE;
    const uint32_t sVh = sKh + 2 * FKTILE;
    const uint32_t sVl = sKh + 3 * FKTILE;

    const int qt = blockIdx.x, hh = blockIdx.y;
    const int b = hh >> 5, h = hh & 31, kvh = h >> 2;
    const int tid = threadIdx.x, wid = tid >> 5, lane = tid & 31;

    const __nv_bfloat16* Qhb = Qh + ((size_t)((b * NH + h) * SEQ) + qt * 128) * HD;
    const __nv_bfloat16* Qlb = Ql + ((size_t)((b * NH + h) * SEQ) + qt * 128) * HD;
    const __nv_bfloat16* Khb = Kh + (size_t)((b * NKV + kvh) * SEQ) * HD;
    const __nv_bfloat16* Klb = Kl + (size_t)((b * NKV + kvh) * SEQ) * HD;
    const __nv_bfloat16* Vhb = Vh + (size_t)((b * NKV + kvh) * SEQ) * HD;
    const __nv_bfloat16* Vlb = Vl + (size_t)((b * NKV + kvh) * SEQ) * HD;

    {
        const int r = tid >> 1, hf = tid & 1;
        const uint4* s0 = (const uint4*)(Qhb + (size_t)r * HD + hf * 32);
        const uint4* s1 = (const uint4*)(Qlb + (size_t)r * HD + hf * 32);
        uint32_t d0 = sQh + r * FROWB + hf * 64;
        uint32_t d1 = sQl + r * FROWB + hf * 64;
#pragma unroll
        for (int i = 0; i < 4; i++) {
            uint4 v = s0[i];
            asm volatile("st.shared.v4.b32 [%0], {%1,%2,%3,%4};"
                         :: "r"(d0 + i * 16), "r"(v.x), "r"(v.y), "r"(v.z), "r"(v.w) : "memory");
            v = s1[i];
            asm volatile("st.shared.v4.b32 [%0], {%1,%2,%3,%4};"
                         :: "r"(d1 + i * 16), "r"(v.x), "r"(v.y), "r"(v.z), "r"(v.w) : "memory");
        }
    }

    const int l8 = lane & 7, mi = lane >> 3;
    const uint32_t qa_off = (uint32_t)(wid * 16 + l8 + ((mi & 1) << 3)) * FROWB
                          + ((mi >> 1) << 4);
    const uint32_t kb_base = (uint32_t)(l8 + ((mi & 1) << 3)) * FROWB + ((mi >> 1) << 4);
    const uint32_t vb_base = (uint32_t)(((mi & 1) << 3) + l8) * FROWB + ((mi >> 1) << 4);

    float m0 = -1e30f, m1 = -1e30f, l0 = 0.f, l1 = 0.f;
    float o[8][4];
#pragma unroll
    for (int j = 0; j < 8; j++)
#pragma unroll
        for (int v = 0; v < 4; v++) o[j][v] = 0.f;

    const int rlo = wid * 16 + (lane >> 2);
    const int rhi = rlo + 8;

    const int ntiles = 2 * qt + 2;
    for (int kt = 0; kt < ntiles; kt++) {
        __syncthreads();
        {
            const int r = tid >> 2, q4 = tid & 3;
            const size_t goff = (size_t)(kt * 64 + r) * HD + q4 * 16;
            const uint32_t dof = r * FROWB + q4 * 32;
            const __nv_bfloat16* gs[4] = { Khb + goff, Klb + goff, Vhb + goff, Vlb + goff };
            const uint32_t ds[4] = { sKh + dof, sKl + dof, sVh + dof, sVl + dof };
#pragma unroll
            for (int t = 0; t < 4; t++) {
                uint4 v0 = *(const uint4*)(gs[t]);
                uint4 v1 = *(const uint4*)(gs[t] + 8);
                asm volatile("st.shared.v4.b32 [%0], {%1,%2,%3,%4};"
                             :: "r"(ds[t]), "r"(v0.x), "r"(v0.y), "r"(v0.z), "r"(v0.w) : "memory");
                asm volatile("st.shared.v4.b32 [%0], {%1,%2,%3,%4};"
                             :: "r"(ds[t] + 16), "r"(v1.x), "r"(v1.y), "r"(v1.z), "r"(v1.w) : "memory");
            }
        }
        __syncthreads();

        float sa[8][4];
#pragma unroll
        for (int j = 0; j < 8; j++)
#pragma unroll
            for (int v = 0; v < 4; v++) sa[j][v] = 0.f;

#pragma unroll
        for (int ks = 0; ks < 4; ks++) {
            uint32_t aqh[4], aql[4];
            ldsm_x4(aqh[0], aqh[1], aqh[2], aqh[3], sQh + qa_off + ks * 32);
            ldsm_x4(aql[0], aql[1], aql[2], aql[3], sQl + qa_off + ks * 32);
#pragma unroll
            for (int p = 0; p < 4; p++) {
                uint32_t addr = kb_base + (uint32_t)(p * 16) * FROWB + ks * 32;
                uint32_t r0, r1, r2, r3;
                uint32_t bh0[2], bh1[2], bl0[2], bl1[2];
                ldsm_x4(r0, r1, r2, r3, sKh + addr);
                bh0[0] = r0; bh0[1] = r2; bh1[0] = r1; bh1[1] = r3;
                ldsm_x4(r0, r1, r2, r3, sKl + addr);
                bl0[0] = r0; bl0[1] = r2; bl1[0] = r1; bl1[1] = r3;
                float* d0 = sa[2 * p];
                float* d1 = sa[2 * p + 1];
                mma_bf16(d0[0], d0[1], d0[2], d0[3], aqh[0], aqh[1], aqh[2], aqh[3], bh0[0], bh0[1]);
                mma_bf16(d0[0], d0[1], d0[2], d0[3], aqh[0], aqh[1], aqh[2], aqh[3], bl0[0], bl0[1]);
                mma_bf16(d0[0], d0[1], d0[2], d0[3], aql[0], aql[1], aql[2], aql[3], bh0[0], bh0[1]);
                mma_bf16(d1[0], d1[1], d1[2], d1[3], aqh[0], aqh[1], aqh[2], aqh[3], bh1[0], bh1[1]);
                mma_bf16(d1[0], d1[1], d1[2], d1[3], aqh[0], aqh[1], aqh[2], aqh[3], bl1[0], bl1[1]);
                mma_bf16(d1[0], d1[1], d1[2], d1[3], aql[0], aql[1], aql[2], aql[3], bh1[0], bh1[1]);
            }
        }

        const int ktd = kt - 2 * qt;
        float mx0 = -1e30f, mx1 = -1e30f;
#pragma unroll
        for (int j = 0; j < 8; j++) {
            const int c0 = 8 * j + (lane & 3) * 2;
#pragma unroll
            for (int v = 0; v < 4; v++) {
                float sc = sa[j][v] * 0.125f;
                if (ktd >= 0) {
                    int col = c0 + (v & 1) + (ktd << 6);
                    int row = (v < 2) ? rlo : rhi;
                    if (col > row) sc = -1e30f;
                }
                sa[j][v] = sc;
            }
            mx0 = fmaxf(mx0, fmaxf(sa[j][0], sa[j][1]));
            mx1 = fmaxf(mx1, fmaxf(sa[j][2], sa[j][3]));
        }
        mx0 = fmaxf(mx0, __shfl_xor_sync(0xffffffffu, mx0, 1));
        mx0 = fmaxf(mx0, __shfl_xor_sync(0xffffffffu, mx0, 2));
        mx1 = fmaxf(mx1, __shfl_xor_sync(0xffffffffu, mx1, 1));
        mx1 = fmaxf(mx1, __shfl_xor_sync(0xffffffffu, mx1, 2));

        const float mn0 = fmaxf(m0, mx0), mn1 = fmaxf(m1, mx1);
        const float al0 = __expf(m0 - mn0), al1 = __expf(m1 - mn1);
        m0 = mn0; m1 = mn1;

        float sum0 = 0.f, sum1 = 0.f;
#pragma unroll
        for (int j = 0; j < 8; j++) {
            float e0 = __expf(sa[j][0] - mn0);
            float e1 = __expf(sa[j][1] - mn0);
            float e2 = __expf(sa[j][2] - mn1);
            float e3 = __expf(sa[j][3] - mn1);
            sa[j][0] = e0; sa[j][1] = e1; sa[j][2] = e2; sa[j][3] = e3;
            sum0 += e0 + e1;
            sum1 += e2 + e3;
        }
        sum0 += __shfl_xor_sync(0xffffffffu, sum0, 1);
        sum0 += __shfl_xor_sync(0xffffffffu, sum0, 2);
        sum1 += __shfl_xor_sync(0xffffffffu, sum1, 1);
        sum1 += __shfl_xor_sync(0xffffffffu, sum1, 2);
        l0 = l0 * al0 + sum0;
        l1 = l1 * al1 + sum1;

#pragma unroll
        for (int j = 0; j < 8; j++) {
            o[j][0] *= al0; o[j][1] *= al0;
            o[j][2] *= al1; o[j][3] *= al1;
        }

#pragma unroll
        for (int kc = 0; kc < 4; kc++) {
            const float* e0 = sa[2 * kc];
            const float* e1 = sa[2 * kc + 1];
            uint32_t ph[4], pl[4];
            ph[0] = pack_bf16(e0[0], e0[1]);
            ph[1] = pack_bf16(e0[2], e0[3]);
            ph[2] = pack_bf16(e1[0], e1[1]);
            ph[3] = pack_bf16(e1[2], e1[3]);
            {
                __nv_bfloat162 t;
                t = *(__nv_bfloat162*)&ph[0];
                pl[0] = pack_bf16(e0[0] - __bfloat162float(t.x), e0[1] - __bfloat162float(t.y));
                t = *(__nv_bfloat162*)&ph[1];
                pl[1] = pack_bf16(e0[2] - __bfloat162float(t.x), e0[3] - __bfloat162float(t.y));
                t = *(__nv_bfloat162*)&ph[2];
                pl[2] = pack_bf16(e1[0] - __bfloat162float(t.x), e1[1] - __bfloat162float(t.y));
                t = *(__nv_bfloat162*)&ph[3];
                pl[3] = pack_bf16(e1[2] - __bfloat162float(t.x), e1[3] - __bfloat162float(t.y));
            }
#pragma unroll
            for (int t4 = 0; t4 < 4; t4++) {
                uint32_t addr = vb_base + (uint32_t)(kc * 16) * FROWB + t4 * 32;
                uint32_t r0, r1, r2, r3;
                uint32_t bh0[2], bh1[2], bl0[2], bl1[2];
                ldsm_x4_t(r0, r1, r2, r3, sVh + addr);
                bh0[0] = r0; bh0[1] = r1; bh1[0] = r2; bh1[1] = r3;
                ldsm_x4_t(r0, r1, r2, r3, sVl + addr);
                bl0[0] = r0; bl0[1] = r1; bl1[0] = r2; bl1[1] = r3;
                float* d0 = o[2 * t4];
                float* d1 = o[2 * t4 + 1];
                mma_bf16(d0[0], d0[1], d0[2], d0[3], ph[0], ph[1], ph[2], ph[3], bh0[0], bh0[1]);
                mma_bf16(d0[0], d0[1], d0[2], d0[3], pl[0], pl[1], pl[2], pl[3], bh0[0], bh0[1]);
                mma_bf16(d0[0], d0[1], d0[2], d0[3], ph[0], ph[1], ph[2], ph[3], bl0[0], bl0[1]);
                mma_bf16(d1[0], d1[1], d1[2], d1[3], ph[0], ph[1], ph[2], ph[3], bh1[0], bh1[1]);
                mma_bf16(d1[0], d1[1], d1[2], d1[3], pl[0], pl[1], pl[2], pl[3], bh1[0], bh1[1]);
                mma_bf16(d1[0], d1[1], d1[2], d1[3], ph[0], ph[1], ph[2], ph[3], bl1[0], bl1[1]);
            }
        }
    }

    const float inv0 = 1.f / l0, inv1 = 1.f / l1;
    const int glo = qt * 128 + rlo;
    const int ghi = glo + 8;
#pragma unroll
    for (int j = 0; j < 8; j++) {
        const int d = 8 * j + (lane & 3) * 2;
        size_t plo = ((size_t)(b * SEQ + glo) * NH + h) * HD + d;
        size_t phi = ((size_t)(b * SEQ + ghi) * NH + h) * HD + d;
        *(__half2*)&O[plo] = __halves2half2(__float2half(o[j][0] * inv0),
                                            __float2half(o[j][1] * inv0));
        *(__half2*)&O[phi] = __halves2half2(__float2half(o[j][2] * inv1),
                                            __float2half(o[j][3] * inv1));
    }
}

// ---------------- launch -----------------------------------------------------
extern "C" void kernel_launch(void* const* d_in, const int* in_sizes, int n_in,
                              void* d_out, int out_size)
{
    const float* x    = (const float*)d_in[0];
    const float* cosT = (const float*)d_in[2];
    const float* sinT = (const float*)d_in[3];
    const float* Wq   = (const float*)d_in[4];
    const float* Wk   = (const float*)d_in[5];
    const float* Wv   = (const float*)d_in[6];
    const float* Wo   = (const float*)d_in[7];

    float* out = (float*)d_out;                         // (B,S,E)
    float* nk  = out + (size_t)BSZ * SEQ * EMB;         // (B,KV,S,D)
    float* nv  = nk + (size_t)BSZ * NKV * SEQ * HD;     // (B,KV,S,D)

    __nv_bfloat16 *qh, *ql, *kh, *kl, *vh, *vl;
    __half *xfh, *xfl, *af, *wqkvf, *wof;
    cudaGetSymbolAddress((void**)&xfh, g_xf_hi);
    cudaGetSymbolAddress((void**)&xfl, g_xf_lo);
    cudaGetSymbolAddress((void**)&af,  g_af);
    cudaGetSymbolAddress((void**)&qh,  g_qh);
    cudaGetSymbolAddress((void**)&ql,  g_ql);
    cudaGetSymbolAddress((void**)&kh,  g_kh);
    cudaGetSymbolAddress((void**)&kl,  g_kl);
    cudaGetSymbolAddress((void**)&vh,  g_vh);
    cudaGetSymbolAddress((void**)&vl,  g_vl);
    cudaGetSymbolAddress((void**)&wqkvf, g_wqkv_f);
    cudaGetSymbolAddress((void**)&wof, g_wo_f);

    cudaFuncSetAttribute(gemm_qkv_kernel,
                         cudaFuncAttributeMaxDynamicSharedMemorySize, QKV_SMEM);
    cudaFuncSetAttribute(gemm_f16_kernel,
                         cudaFuncAttributeMaxDynamicSharedMemorySize, 2 * F16_STAGE);
    cudaFuncSetAttribute(flash_mma_kernel,
                         cudaFuncAttributeMaxDynamicSharedMemorySize, FSMEM);

    const int M = BSZ * SEQ;          // 4096
    const size_t NX = (size_t)M * EMB;

    // split x (fp16 hi/lo) + weights (QKV packed [3072 x 2048] fp16; Wo fp16)
    split_f16_kernel<<<(int)(NX / 4 / 256), 256>>>((const float4*)x, xfh, xfl);
    wt_f16_kernel<<<dim3(EMB / 32, EMB / 32), dim3(32, 8)>>>(Wq, wqkvf, EMB, EMB);
    wt_f16_kernel<<<dim3(KVD / 32, EMB / 32), dim3(32, 8)>>>(
        Wk, wqkvf + (size_t)EMB * EMB, EMB, KVD);
    wt_f16_kernel<<<dim3(KVD / 32, EMB / 32), dim3(32, 8)>>>(
        Wv, wqkvf + (size_t)(EMB + KVD) * EMB, EMB, KVD);
    wt_f16_kernel<<<dim3(EMB / 32, EMB / 32), dim3(32, 8)>>>(Wo, wof, EMB, EMB);

    // fused QKV projection (2-term fp16) + RoPE/split epilogue
    gemm_qkv_kernel<<<dim3(QKVN / 128, M / 128), 256, QKV_SMEM>>>(
        xfh, xfl, wqkvf, EMB, qh, ql, kh, kl, vh, vl, nk, nv, cosT, sinT);

    // attention on tensor cores (BR=128, writes fp16 output)
    flash_mma_kernel<<<dim3(SEQ / 128, BSZ * NH), 256, FSMEM>>>(
        qh, ql, kh, kl, vh, vl, af);

    // output projection: single-term fp16 GEMM
    gemm_f16_kernel<<<dim3(EMB / 128, M / 128), 256, 2 * F16_STAGE>>>(
        af, wof, out, M, EMB, EMB);
}